// round 14
// baseline (speedup 1.0000x reference)
#include <cuda_runtime.h>
#include <cuda_bf16.h>
#include <cstdint>
#include <math.h>

#define SEQ 2048
#define DIMD 2048
#define FDM 512

// ------------------------- fp32 scratch (device globals) --------------------
__device__ float g_qkv [(size_t)4096 * 6144];
__device__ float g_lrpre[(size_t)4096 * 12];
__device__ float g_lr  [(size_t)4096 * 12];
__device__ float g_w02 [(size_t)8 * 1024 * FDM];
__device__ float g_w1  [(size_t)8 * FDM * FDM];
__device__ float g_gh  [(size_t)8 * 1024 * 1024];
__device__ float g_dh  [(size_t)8 * 1024 * FDM];
__device__ float g_ttt [(size_t)8 * SEQ * FDM];
__device__ float g_sum [(size_t)4096 * 2048];

// ---------------------- tf32 (pre-rounded fp32) operands --------------------
__device__ float g_hx_t [(size_t)4096 * 2048];
__device__ float g_wq_t [(size_t)6144 * 2048];
__device__ float g_wo_t [(size_t)2048 * 2048];
__device__ float g_fq_t [(size_t)8 * SEQ * FDM];
__device__ float g_fk_t [(size_t)8 * SEQ * FDM];
__device__ float g_fv_t [(size_t)8 * SEQ * FDM];
__device__ float g_w02_t[(size_t)8 * 1024 * FDM];
__device__ float g_w1_t [(size_t)8 * FDM * FDM];
__device__ float g_dgp_t[(size_t)8 * 1024 * 1024];
__device__ float g_vl_t [(size_t)8 * 1024 * FDM];
__device__ float g_ht_t [(size_t)8 * 1024 * FDM];
__device__ float g_hn_t [(size_t)8 * 1024 * FDM];
__device__ float g_sm_t [(size_t)4096 * 2048];

// ------------------- bf16 hi/lo (attention only) ----------------------------
__device__ __nv_bfloat16 g_aq_h[(size_t)4096*2048], g_aq_l[(size_t)4096*2048];
__device__ __nv_bfloat16 g_ak_h[(size_t)4096*2048], g_ak_l[(size_t)4096*2048];
__device__ __nv_bfloat16 g_av_h[(size_t)4096*2048], g_av_l[(size_t)4096*2048];

// ------------------------------ helpers -------------------------------------
__device__ __forceinline__ uint32_t smem_u32(const void* p) {
    uint32_t a;
    asm("{ .reg .u64 t; cvta.to.shared.u64 t, %1; cvt.u32.u64 %0, t; }" : "=r"(a) : "l"(p));
    return a;
}
__device__ __forceinline__ void cpa16(uint32_t s, const void* g) {
    asm volatile("cp.async.cg.shared.global [%0], [%1], 16;" :: "r"(s), "l"(g));
}
#define CP_COMMIT() asm volatile("cp.async.commit_group;" ::: "memory")
#define MMA16816(d, a, b0, b1) \
    asm volatile("mma.sync.aligned.m16n8k16.row.col.f32.bf16.bf16.f32 " \
        "{%0,%1,%2,%3}, {%4,%5,%6,%7}, {%8,%9}, {%0,%1,%2,%3};" \
        : "+f"((d)[0]), "+f"((d)[1]), "+f"((d)[2]), "+f"((d)[3]) \
        : "r"((a)[0]), "r"((a)[1]), "r"((a)[2]), "r"((a)[3]), "r"(b0), "r"(b1))
#define MMATF(d, a, b0, b1) \
    asm volatile("mma.sync.aligned.m16n8k8.row.col.f32.tf32.tf32.f32 " \
        "{%0,%1,%2,%3}, {%4,%5,%6,%7}, {%8,%9}, {%0,%1,%2,%3};" \
        : "+f"((d)[0]), "+f"((d)[1]), "+f"((d)[2]), "+f"((d)[3]) \
        : "r"((a)[0]), "r"((a)[1]), "r"((a)[2]), "r"((a)[3]), "r"(b0), "r"(b1))
__device__ __forceinline__ void ldmx4(uint32_t* r, uint32_t addr) {
    asm volatile("ldmatrix.sync.aligned.m8n8.x4.shared.b16 {%0,%1,%2,%3}, [%4];"
        : "=r"(r[0]), "=r"(r[1]), "=r"(r[2]), "=r"(r[3]) : "r"(addr));
}
__device__ __forceinline__ void ldmx4t(uint32_t* r, uint32_t addr) {
    asm volatile("ldmatrix.sync.aligned.m8n8.x4.trans.shared.b16 {%0,%1,%2,%3}, [%4];"
        : "=r"(r[0]), "=r"(r[1]), "=r"(r[2]), "=r"(r[3]) : "r"(addr));
}
__device__ __forceinline__ void split_w(float v, __nv_bfloat16* h, __nv_bfloat16* l, long i) {
    __nv_bfloat16 hv = __float2bfloat16_rn(v);
    h[i] = hv;
    l[i] = __float2bfloat16_rn(v - __bfloat162float(hv));
}
__device__ __forceinline__ float to_tf32(float v) {
    uint32_t u;
    asm("cvt.rna.tf32.f32 %0, %1;" : "=r"(u) : "f"(v));
    return __uint_as_float(u);
}
__device__ __forceinline__ uint32_t lds_u32(uint32_t addr) {
    uint32_t v;
    asm volatile("ld.shared.b32 %0, [%1];" : "=r"(v) : "r"(addr));
    return v;
}
__device__ __forceinline__ uint32_t pack_bf2(float a, float b) {
    __nv_bfloat162 t;
    t.x = __float2bfloat16_rn(a);
    t.y = __float2bfloat16_rn(b);
    return *(uint32_t*)&t;
}

// ------------- TF32 mma.sync batched GEMM (256x128 tile, 3-stage) -----------
struct GP {
    const float* A; const float* B;
    float* C; float* Ct;
    int M, N, K, lda, ldb;
    long sA, sB, sC;
    int gx, gy;
};

// tile: 256(M) x 128(N); 8 warps (wm 0..3 x wn 0..1), warp tile 64x64
template<int AT, int BT, bool ACC, bool SPLIT>
__device__ __forceinline__ void gemm_body(const GP p, int bz)
{
    if ((int)blockIdx.x >= p.gx || (int)blockIdx.y >= p.gy) return;
    constexpr int SA = AT ? 32 * 1056 : 256 * 144;   // 33792 : 36864
    constexpr int SB = BT ? 32 * 544  : 128 * 144;   // 17408 : 18432
    constexpr int STAGE = SA + SB;
    extern __shared__ char smem[];
    uint32_t sb = smem_u32(smem);
    int tid = threadIdx.x, lane = tid & 31, wid = tid >> 5;
    int wm = wid >> 1, wn = wid & 1;
    const float* a = p.A + (long)bz * p.sA;
    const float* b = p.B + (long)bz * p.sB;
    int m0 = blockIdx.y << 8, n0 = blockIdx.x << 7;
    int lda = p.lda, ldb = p.ldb;

    float acc[4][8][4];
    #pragma unroll
    for (int i = 0; i < 4; ++i)
        #pragma unroll
        for (int j = 0; j < 8; ++j)
            #pragma unroll
            for (int q = 0; q < 4; ++q) acc[i][j][q] = 0.f;

    int Lm = lane >> 3, Lr = lane & 7;
    uint32_t aoff = (uint32_t)(((Lm & 1) * 8 + Lr) * 144 + (Lm >> 1) * 16);
    uint32_t boff = (uint32_t)(((Lm >> 1) * 8 + Lr) * 144 + (Lm & 1) * 16);

    auto issue = [&](int buf, int k0) {
        uint32_t st = sb + buf * STAGE;
        #pragma unroll
        for (int j = 0; j < 8; ++j) {
            int u = tid + j * 256;
            uint32_t so; long g;
            if (AT == 0) { int r = u >> 3, s = u & 7;   so = r * 144 + s * 16;
                           g = (long)(m0 + r) * lda + k0 + s * 4; }
            else         { int r = u >> 6, s = u & 63;  so = r * 1056 + s * 16;
                           g = (long)(k0 + r) * lda + m0 + s * 4; }
            cpa16(st + so, a + g);
        }
        #pragma unroll
        for (int j = 0; j < 4; ++j) {
            int u = tid + j * 256;
            uint32_t so; long g;
            if (BT == 0) { int r = u >> 3, s = u & 7;   so = r * 144 + s * 16;
                           g = (long)(n0 + r) * ldb + k0 + s * 4; }
            else         { int r = u >> 5, s = u & 31;  so = r * 544 + s * 16;
                           g = (long)(k0 + r) * ldb + n0 + s * 4; }
            cpa16(st + SA + so, b + g);
        }
        CP_COMMIT();
    };

    const int n = p.K >> 5;
    issue(0, 0);
    if (n > 1) issue(1, 32);
    int buf = 0;
    for (int i = 0; i < n; ++i) {
        if (i + 1 < n) asm volatile("cp.async.wait_group 1;" ::: "memory");
        else           asm volatile("cp.async.wait_group 0;" ::: "memory");
        __syncthreads();
        uint32_t st = sb + buf * STAGE;
        uint32_t stB = st + SA;
        #pragma unroll
        for (int kk = 0; kk < 32; kk += 8) {
            uint32_t af[4][4];
            #pragma unroll
            for (int mt = 0; mt < 4; ++mt) {
                if (AT == 0) {
                    ldmx4(af[mt], st + (wm * 64 + mt * 16) * 144 + kk * 4 + aoff);
                } else {
                    uint32_t ra = st + (kk + (lane & 3)) * 1056
                                + (wm * 64 + mt * 16 + (lane >> 2)) * 4;
                    af[mt][0] = lds_u32(ra);
                    af[mt][1] = lds_u32(ra + 32);
                    af[mt][2] = lds_u32(ra + 4 * 1056);
                    af[mt][3] = lds_u32(ra + 4 * 1056 + 32);
                }
            }
            uint32_t bf_[8][2];
            if (BT == 0) {
                #pragma unroll
                for (int pp = 0; pp < 4; ++pp) {
                    uint32_t r4[4];
                    ldmx4(r4, stB + (wn * 64 + pp * 16) * 144 + kk * 4 + boff);
                    bf_[pp * 2 + 0][0] = r4[0]; bf_[pp * 2 + 0][1] = r4[1];
                    bf_[pp * 2 + 1][0] = r4[2]; bf_[pp * 2 + 1][1] = r4[3];
                }
            } else {
                #pragma unroll
                for (int nt = 0; nt < 8; ++nt) {
                    uint32_t rb = stB + (kk + (lane & 3)) * 544
                                + (wn * 64 + nt * 8 + (lane >> 2)) * 4;
                    bf_[nt][0] = lds_u32(rb);
                    bf_[nt][1] = lds_u32(rb + 4 * 544);
                }
            }
            #pragma unroll
            for (int nt = 0; nt < 8; ++nt)
                #pragma unroll
                for (int mt = 0; mt < 4; ++mt)
                    MMATF(acc[mt][nt], af[mt], bf_[nt][0], bf_[nt][1]);
        }
        if (i + 2 < n) issue((i + 2) % 3, (i + 2) * 32);
        buf = (buf == 2) ? 0 : buf + 1;
    }
    float* c = p.C + (long)bz * p.sC;
    float* ct = SPLIT ? p.Ct + (long)bz * p.sC : nullptr;
    int N = p.N;
    #pragma unroll
    for (int mt = 0; mt < 4; ++mt) {
        #pragma unroll
        for (int nt = 0; nt < 8; ++nt) {
            long r0 = m0 + wm * 64 + mt * 16 + (lane >> 2);
            int  cc = n0 + wn * 64 + nt * 8 + (lane & 3) * 2;
            long o0 = r0 * (long)N + cc;
            long o1 = (r0 + 8) * (long)N + cc;
            float v00 = acc[mt][nt][0], v01 = acc[mt][nt][1];
            float v10 = acc[mt][nt][2], v11 = acc[mt][nt][3];
            if (ACC) {
                float2 t0 = *(float2*)(c + o0), t1 = *(float2*)(c + o1);
                v00 += t0.x; v01 += t0.y; v10 += t1.x; v11 += t1.y;
            }
            *(float2*)(c + o0) = make_float2(v00, v01);
            *(float2*)(c + o1) = make_float2(v10, v11);
            if (SPLIT) {
                *(float2*)(ct + o0) = make_float2(to_tf32(v00), to_tf32(v01));
                *(float2*)(ct + o1) = make_float2(to_tf32(v10), to_tf32(v11));
            }
        }
    }
}

__global__ void __launch_bounds__(256, 1) tf_nt(GP p) {
    gemm_body<0, 0, false, false>(p, blockIdx.z);
}
__global__ void __launch_bounds__(256, 1) tf_pack_fwd(GP p1, GP p2, int z1) {
    if ((int)blockIdx.z < z1) gemm_body<0, 0, false, false>(p1, blockIdx.z);
    else                      gemm_body<0, 1, false, false>(p2, blockIdx.z - z1);
}
__global__ void __launch_bounds__(256, 1) tf_pack_upd(GP p1, GP p2, int z1) {
    if ((int)blockIdx.z < z1) gemm_body<1, 1, true, true>(p1, blockIdx.z);
    else                      gemm_body<1, 1, true, true>(p2, blockIdx.z - z1);
}
__global__ void __launch_bounds__(256, 1) tf_pack3(GP p1, GP p2, GP p3, int z1, int z2) {
    int z = blockIdx.z;
    if (z < z1)            gemm_body<0, 0, false, false>(p1, z);
    else if (z < z1 + z2)  gemm_body<0, 0, false, false>(p2, z - z1);
    else                   gemm_body<0, 1, false, false>(p3, z - z1 - z2);
}

// ------------------------ conversion kernel ---------------------------------
__global__ void cvt_tf(const float* __restrict__ x, float* __restrict__ o, long n)
{
    long i = ((long)blockIdx.x * 256 + threadIdx.x) * 4;
    if (i >= n) return;
    float4 v = *(const float4*)(x + i);
    float4 w;
    w.x = to_tf32(v.x); w.y = to_tf32(v.y); w.z = to_tf32(v.z); w.w = to_tf32(v.w);
    *(float4*)(o + i) = w;
}

// ---------------- small SGEMM for the N=12 lr GEMM --------------------------
__global__ void lr_gemm(const float* __restrict__ A, const float* __restrict__ B,
                        float* __restrict__ C)
{
    __shared__ float bs[12][128];
    int row = blockIdx.x * 2 + (threadIdx.x >> 7);
    int tid = threadIdx.x & 127;
    float acc[12];
    #pragma unroll
    for (int c = 0; c < 12; ++c) acc[c] = 0.f;
    for (int k0 = 0; k0 < 2048; k0 += 128) {
        if (threadIdx.x < 128)
            #pragma unroll
            for (int c = 0; c < 12; ++c) bs[c][tid] = B[c * 2048 + k0 + tid];
        __syncthreads();
        float a = A[(long)row * 2048 + k0 + tid];
        #pragma unroll
        for (int c = 0; c < 12; ++c) acc[c] += a * bs[c][tid];
        __syncthreads();
    }
    __shared__ float red[2][12][4];
    #pragma unroll
    for (int c = 0; c < 12; ++c) {
        float v = acc[c];
        #pragma unroll
        for (int o = 16; o > 0; o >>= 1) v += __shfl_down_sync(0xffffffffu, v, o);
        if ((tid & 31) == 0) red[threadIdx.x >> 7][c][tid >> 5] = v;
    }
    __syncthreads();
    if (tid < 12) {
        int w = threadIdx.x >> 7;
        C[(long)row * 12 + tid] = red[w][tid][0] + red[w][tid][1] + red[w][tid][2] + red[w][tid][3];
    }
}

// ------------------------- block reduce (256 thr) ---------------------------
__device__ __forceinline__ float blockReduceSum(float v, float* sred)
{
    int lane = threadIdx.x & 31;
    #pragma unroll
    for (int o = 16; o > 0; o >>= 1) v += __shfl_down_sync(0xffffffffu, v, o);
    if (lane == 0) sred[threadIdx.x >> 5] = v;
    __syncthreads();
    if (threadIdx.x < 8) {
        float r = sred[threadIdx.x];
        #pragma unroll
        for (int o = 4; o > 0; o >>= 1) r += __shfl_down_sync(0xffu, r, o);
        if (threadIdx.x == 0) sred[0] = r;
    }
    __syncthreads();
    float out = sred[0];
    __syncthreads();
    return out;
}

// --------- prep: rmsnorm+rope + silu/L2 + lr ---------------------------------
__global__ void prep_kernel(const float* __restrict__ qkv, const float* __restrict__ lrpre,
                            const float* __restrict__ qnw, const float* __restrict__ knw,
                            const float* __restrict__ qksc, const float* __restrict__ qkof,
                            const float* __restrict__ lrb, float base_lr_inv,
                            __nv_bfloat16* __restrict__ aqh, __nv_bfloat16* __restrict__ aql,
                            __nv_bfloat16* __restrict__ akh, __nv_bfloat16* __restrict__ akl,
                            __nv_bfloat16* __restrict__ avh, __nv_bfloat16* __restrict__ avl,
                            float* __restrict__ fqt, float* __restrict__ fkt,
                            float* __restrict__ fvt, float* __restrict__ lrout)
{
    __shared__ float s_q[2048];
    __shared__ float s_k[2048];
    __shared__ float sred[8];
    int row = blockIdx.x;
    int b = row >> 11, t = row & 2047;
    int tid = threadIdx.x;
    const float* qr = qkv + (long)row * 6144;
    const float* kr = qr + 2048;
    const float* vr = qr + 4096;
    const float qscale = 0.088388347648318447f * 1.4426950408889634f;

    float qv[8], kv[8], fqv[8], fkv[8], fvv[8];
    float sq = 0.f, sk = 0.f;
    float p2q[4] = {0, 0, 0, 0}, p2k[4] = {0, 0, 0, 0};
    #pragma unroll
    for (int j = 0; j < 8; ++j) {
        int i = j * 256 + tid;
        float q = qr[i], k = kr[i], v = vr[i];
        qv[j] = q; kv[j] = k;
        sq += q * q; sk += k * k;
        float fqe = (q / (1.f + expf(-q))) * qksc[i * 2 + 0] + qkof[i * 2 + 0];
        float fke = (k / (1.f + expf(-k))) * qksc[i * 2 + 1] + qkof[i * 2 + 1];
        fqv[j] = fqe; fkv[j] = fke; fvv[j] = v / (1.f + expf(-v));
        p2q[j >> 1] += fqe * fqe;
        p2k[j >> 1] += fke * fke;
        split_w(v, avh, avl, (long)row * DIMD + i);
    }
    float SQ = blockReduceSum(sq, sred);
    float SK = blockReduceSum(sk, sred);
    float G2Q[4], G2K[4];
    #pragma unroll
    for (int g = 0; g < 4; ++g) G2Q[g] = blockReduceSum(p2q[g], sred);
    #pragma unroll
    for (int g = 0; g < 4; ++g) G2K[g] = blockReduceSum(p2k[g], sred);
    float rq = rsqrtf(SQ * (1.f / 2048.f) + 1e-6f);
    float rk = rsqrtf(SK * (1.f / 2048.f) + 1e-6f);
    #pragma unroll
    for (int j = 0; j < 8; ++j) {
        int i = j * 256 + tid;
        s_q[i] = qv[j] * rq * qnw[i];
        s_k[i] = kv[j] * rk * knw[i];
        int g = j >> 1;
        long fb = (((long)(b * 4 + g)) * SEQ + t) * FDM + (i & 511);
        fqt[fb] = to_tf32(fqv[j] / (sqrtf(G2Q[g]) + 1e-12f));
        fkt[fb] = to_tf32(fkv[j] / (sqrtf(G2K[g]) + 1e-12f));
        fvt[fb] = to_tf32(fvv[j]);
    }
    __syncthreads();
    #pragma unroll
    for (int j = 0; j < 8; ++j) {
        int i = j * 256 + tid;
        int pos = i & 127;
        int fi = pos & 63;
        float invf = expf(-(float)fi * (logf(500000.f) / 64.f));
        float sn, cs;
        sincosf((float)t * invf, &sn, &cs);
        float oq, ok_;
        if (pos < 64) {
            oq  = s_q[i] * cs - s_q[i + 64] * sn;
            ok_ = s_k[i] * cs - s_k[i + 64] * sn;
        } else {
            oq  = s_q[i] * cs + s_q[i - 64] * sn;
            ok_ = s_k[i] * cs + s_k[i - 64] * sn;
        }
        split_w(oq * qscale, aqh, aql, (long)row * DIMD + i);
        split_w(ok_, akh, akl, (long)row * DIMD + i);
    }
    if (tid < 12) {
        float x = lrpre[(long)row * 12 + tid] + lrb[tid] + base_lr_inv;
        lrout[(long)row * 12 + tid] = (x > 20.f) ? x : log1pf(expf(x));
    }
}

// ------------- HMMA flash attention, register softmax (4 warps) --------------
#define ATS 272
#define O_QH 0
#define O_QL 17408
#define O_KH 34816
#define O_KL 52224
#define O_VH 69632
#define O_VL 87040
#define ATTN_SMEM 104448

__global__ void __launch_bounds__(128, 2)
attn_mma(const __nv_bfloat16* __restrict__ Qh, const __nv_bfloat16* __restrict__ Ql,
         const __nv_bfloat16* __restrict__ Kh, const __nv_bfloat16* __restrict__ Kl,
         const __nv_bfloat16* __restrict__ Vh, const __nv_bfloat16* __restrict__ Vl,
         float* __restrict__ O)
{
    extern __shared__ char smc[];
    uint32_t sb = smem_u32(smc);
    int tid = threadIdx.x, lane = tid & 31, wid = tid >> 5;
    int q0 = blockIdx.x << 6, h = blockIdx.y, b = blockIdx.z;
    int wr = wid * 16;
    uint32_t a_row = (lane & 7) + ((lane >> 3) & 1) * 8;
    uint32_t a_kb  = ((lane >> 4) & 1) * 16;
    uint32_t b_row = (lane & 7) + ((lane >> 4) & 1) * 8;
    uint32_t b_kb  = ((lane >> 3) & 1) * 16;
    uint32_t b_kr  = (lane & 7) + ((lane >> 3) & 1) * 8;
    uint32_t b_no  = ((lane >> 4) & 1) * 8;

    #pragma unroll
    for (int j = 0; j < 8; ++j) {
        int u = tid + j * 128;
        int r = u >> 4, s = u & 15;
        long g = ((long)(b * SEQ + q0 + r)) * DIMD + h * 128 + s * 8;
        cpa16(sb + O_QH + r * ATS + s * 16, Qh + g);
        cpa16(sb + O_QL + r * ATS + s * 16, Ql + g);
    }
    CP_COMMIT();

    float oacc[16][4];
    #pragma unroll
    for (int i = 0; i < 16; ++i)
        #pragma unroll
        for (int q = 0; q < 4; ++q) oacc[i][q] = 0.f;
    float m_lo = -INFINITY, m_hi = -INFINITY, l_lo = 0.f, l_hi = 0.f;

    int r_lo = q0 + wr + (lane >> 2);
    int r_hi = r_lo + 8;

    int kt_hi2 = q0 >> 6;
    int kt_lo2 = (q0 >= 1024) ? ((q0 - 1023) >> 6) : 0;
    for (int kt = kt_lo2; kt <= kt_hi2; ++kt) {
        int j0 = kt << 6;
        __syncthreads();
        #pragma unroll
        for (int j = 0; j < 8; ++j) {
            int u = tid + j * 128;
            int r = u >> 4, s = u & 15;
            long g = ((long)(b * SEQ + j0 + r)) * DIMD + h * 128 + s * 8;
            uint32_t so = r * ATS + s * 16;
            cpa16(sb + O_KH + so, Kh + g);
            cpa16(sb + O_KL + so, Kl + g);
            cpa16(sb + O_VH + so, Vh + g);
            cpa16(sb + O_VL + so, Vl + g);
        }
        CP_COMMIT();
        asm volatile("cp.async.wait_group 0;" ::: "memory");
        __syncthreads();

        float sacc[8][4];
        #pragma unroll
        for (int i = 0; i < 8; ++i)
            #pragma unroll
            for (int q = 0; q < 4; ++q) sacc[i][q] = 0.f;
        #pragma unroll
        for (int kk = 0; kk < 8; ++kk) {
            uint32_t ah4[4], al4[4];
            uint32_t ra = sb + O_QH + (wr + a_row) * ATS + kk * 32 + a_kb;
            ldmx4(ah4, ra);
            ldmx4(al4, ra + (O_QL - O_QH));
            uint32_t bh4[4][4], bl4[4][4];
            #pragma unroll
            for (int p = 0; p < 4; ++p) {
                uint32_t rb = sb + O_KH + (p * 16 + b_row) * ATS + kk * 32 + b_kb;
                ldmx4(bh4[p], rb);
                ldmx4(bl4[p], rb + (O_KL - O_KH));
            }
            #pragma unroll
            for (int nt = 0; nt < 8; ++nt) {
                uint32_t b0h = bh4[nt >> 1][(nt & 1) * 2 + 0];
                uint32_t b1h = bh4[nt >> 1][(nt & 1) * 2 + 1];
                uint32_t b0l = bl4[nt >> 1][(nt & 1) * 2 + 0];
                uint32_t b1l = bl4[nt >> 1][(nt & 1) * 2 + 1];
                MMA16816(sacc[nt], ah4, b0h, b1h);
                MMA16816(sacc[nt], ah4, b0l, b1l);
                MMA16816(sacc[nt], al4, b0h, b1h);
            }
        }
        float tmax_lo = -INFINITY, tmax_hi = -INFINITY;
        #pragma unroll
        for (int nt = 0; nt < 8; ++nt) {
            #pragma unroll
            for (int e = 0; e < 2; ++e) {
                int col = j0 + nt * 8 + (lane & 3) * 2 + e;
                bool ok0 = (col <= r_lo) && (r_lo - col < 1024);
                bool ok1 = (col <= r_hi) && (r_hi - col < 1024);
                sacc[nt][e]     = ok0 ? sacc[nt][e]     : -INFINITY;
                sacc[nt][2 + e] = ok1 ? sacc[nt][2 + e] : -INFINITY;
                tmax_lo = fmaxf(tmax_lo, sacc[nt][e]);
                tmax_hi = fmaxf(tmax_hi, sacc[nt][2 + e]);
            }
        }
        tmax_lo = fmaxf(tmax_lo, __shfl_xor_sync(0xffffffffu, tmax_lo, 1));
        tmax_lo = fmaxf(tmax_lo, __shfl_xor_sync(0xffffffffu, tmax_lo, 2));
        tmax_hi = fmaxf(tmax_hi, __shfl_xor_sync(0xffffffffu, tmax_hi, 1));
        tmax_hi = fmaxf(tmax_hi, __shfl_xor_sync(0xffffffffu, tmax_hi, 2));
        float mt_lo = fmaxf(m_lo, tmax_lo);
        float mt_hi = fmaxf(m_hi, tmax_hi);
        float mte_lo = (mt_lo > -INFINITY) ? mt_lo : 0.f;
        float mte_hi = (mt_hi > -INFINITY) ? mt_hi : 0.f;
        float corr_lo = exp2f(m_lo - mte_lo);
        float corr_hi = exp2f(m_hi - mte_hi);

        uint32_t ph[4][4], pl[4][4];
        float ls_lo = 0.f, ls_hi = 0.f;
        #pragma unroll
        for (int k2 = 0; k2 < 4; ++k2) {
            #pragma unroll
            for (int half = 0; half < 2; ++half) {
                int nt = k2 * 2 + half;
                float p00 = exp2f(sacc[nt][0] - mte_lo);
                float p01 = exp2f(sacc[nt][1] - mte_lo);
                float p10 = exp2f(sacc[nt][2] - mte_hi);
                float p11 = exp2f(sacc[nt][3] - mte_hi);
                ls_lo += p00 + p01;
                ls_hi += p10 + p11;
                uint32_t h0 = pack_bf2(p00, p01);
                uint32_t h1 = pack_bf2(p10, p11);
                __nv_bfloat162 hb0 = *(__nv_bfloat162*)&h0;
                __nv_bfloat162 hb1 = *(__nv_bfloat162*)&h1;
                uint32_t l0 = pack_bf2(p00 - __bfloat162float(hb0.x),
                                       p01 - __bfloat162float(hb0.y));
                uint32_t l1 = pack_bf2(p10 - __bfloat162float(hb1.x),
                                       p11 - __bfloat162float(hb1.y));
                ph[k2][half * 2 + 0] = h0; ph[k2][half * 2 + 1] = h1;
                pl[k2][half * 2 + 0] = l0; pl[k2][half * 2 + 1] = l1;
            }
        }
        ls_lo += __shfl_xor_sync(0xffffffffu, ls_lo, 1);
        ls_lo += __shfl_xor_sync(0xffffffffu, ls_lo, 2);
        ls_hi += __shfl_xor_sync(0xffffffffu, ls_hi, 1);
        ls_hi += __shfl_xor_sync(0xffffffffu, ls_hi, 2);
        l_lo = l_lo * corr_lo + ls_lo;
        l_hi = l_hi * corr_hi + ls_hi;
        m_lo = mt_lo; m_hi = mt_hi;

        #pragma unroll
        for (int nt = 0; nt < 16; ++nt) {
            oacc[nt][0] *= corr_lo; oacc[nt][1] *= corr_lo;
            oacc[nt][2] *= corr_hi; oacc[nt][3] *= corr_hi;
        }
        #pragma unroll
        for (int k2 = 0; k2 < 4; ++k2) {
            #pragma unroll
            for (int p2 = 0; p2 < 8; ++p2) {
                uint32_t vh4[4], vl4[4];
                uint32_t rb = sb + O_VH + (k2 * 16 + b_kr) * ATS + (p2 * 16 + b_no) * 2;
                ldmx4t(vh4, rb);
                ldmx4t(vl4, rb + (O_VL - O_VH));
                #pragma unroll
                for (int sub = 0; sub < 2; ++sub) {
                    int nt = p2 * 2 + sub;
                    uint32_t b0h = vh4[sub * 2], b1h = vh4[sub * 2 + 1];
                    uint32_t b0l = vl4[sub * 2], b1l = vl4[sub * 2 + 1];
                    MMA16816(oacc[nt], ph[k2], b0h, b1h);
                    MMA16816(oacc[nt], ph[k2], b0l, b1l);
                    MMA16816(oacc[nt], pl[k2], b0h, b1h);
                }
            }
        }
    }
    float rl0 = 1.f / l_lo, rl1 = 1.f / l_hi;
    #pragma unroll
    for (int nt = 0; nt < 16; ++nt) {
        int col = nt * 8 + (lane & 3) * 2;
        long o0 = ((long)(b * SEQ + r_lo)) * 2048 + h * 128 + col;
        long o1 = ((long)(b * SEQ + r_hi)) * 2048 + h * 128 + col;
        *(float2*)(O + o0) = make_float2(oacc[nt][0] * rl0, oacc[nt][1] * rl0);
        *(float2*)(O + o1) = make_float2(oacc[nt][2] * rl1, oacc[nt][3] * rl1);
    }
}

// --------------------------- TTT helper kernels -----------------------------
__global__ void copyw(const float* __restrict__ w0, const float* __restrict__ w1,
                      const float* __restrict__ w2,
                      float* __restrict__ o02, float* __restrict__ o02t,
                      float* __restrict__ o1, float* __restrict__ o1t)
{
    long idx = (long)blockIdx.x * 256 + threadIdx.x;
    int col = idx & 511;
    int row = (idx >> 9) & 1023;
    int h = (idx >> 19) & 3;
    long src = (long)h * 262144 + (long)(row & 511) * 512 + col;
    float v = (row < 512) ? w0[src] : w2[src];
    o02[idx] = v;
    o02t[idx] = to_tf32(v);
    if (idx < (long)2 * 1024 * 1024) {
        float v1 = w1[idx & ((long)4 * 262144 - 1)];
        o1[idx] = v1;
        o1t[idx] = to_tf32(v1);
    }
}

__global__ void elem2(const float* __restrict__ fvt, const float* __restrict__ lr,
                      const float* __restrict__ gh, const float* __restrict__ dhin,
                      float* __restrict__ dgpt, float* __restrict__ vlt,
                      float* __restrict__ htt, int ck0)
{
    long idx = (long)blockIdx.x * 256 + threadIdx.x;
    int col = idx & 511;
    long tt = idx >> 9;
    int c = tt & 1023, bh = tt >> 10;
    int b = bh >> 2, h = bh & 3;
    long row = (long)b * SEQ + ck0 + c;
    float l0 = lr[row * 12 + h], l1 = lr[row * 12 + 4 + h], l2 = lr[row * 12 + 8 + h];
    long gi = (long)bh * 1048576 + (long)c * 1024 + col;
    float g = gh[gi], hp = gh[gi + 512], d = dhin[idx];
    float sig = 1.f / (1.f + expf(-g));
    float sg = g * sig;
    htt[idx] = to_tf32(sg * hp);
    float v = fvt[((long)bh * SEQ + ck0 + c) * FDM + col];
    dgpt[gi]       = to_tf32(d * hp * (sig * (1.f + g * (1.f - sig))) * l0);
    dgpt[gi + 512] = to_tf32(d * sg * l2);
    vlt[idx]       = to_tf32(v * l1);
}

__global__ void elem3(const float* __restrict__ gh, float* __restrict__ hnt)
{
    long idx = (long)blockIdx.x * 256 + threadIdx.x;
    int col = idx & 511;
    long tt = idx >> 9;
    int c = tt & 1023, bh = tt >> 10;
    long gi = (long)bh * 1048576 + (long)c * 1024 + col;
    float g = gh[gi];
    hnt[idx] = to_tf32((g / (1.f + expf(-g))) * gh[gi + 512]);
}

// -------------------- ttt rmsnorm + add attention result --------------------
__global__ void post_kernel(const float* __restrict__ ttt, const float* __restrict__ tw,
                            const float* __restrict__ sum, float* __restrict__ smt)
{
    __shared__ float sr[4];
    int fh = blockIdx.x, row = blockIdx.y;
    int b = row >> 11, t = row & 2047;
    int bh = b * 4 + fh;
    const float* src = ttt + ((long)bh * SEQ + t) * FDM;
    int tid = threadIdx.x;
    float v[4], ss = 0.f;
    #pragma unroll
    for (int j = 0; j < 4; ++j) { v[j] = src[tid + 128 * j]; ss += v[j] * v[j]; }
    #pragma unroll
    for (int o = 16; o > 0; o >>= 1) ss += __shfl_down_sync(0xffffffffu, ss, o);
    if ((tid & 31) == 0) sr[tid >> 5] = ss;
    __syncthreads();
    float tot = sr[0] + sr[1] + sr[2] + sr[3];
    float r = rsqrtf(tot * (1.f / 512.f) + 1e-6f);
    #pragma unroll
    for (int j = 0; j < 4; ++j) {
        int i = tid + 128 * j;
        long o = (long)row * 2048 + fh * 512 + i;
        smt[o] = to_tf32(sum[o] + v[j] * r * tw[i]);
    }
}

// --------------------------------- launch -----------------------------------
#define GSYM(p, s) cudaGetSymbolAddress((void**)&(p), s)

extern "C" void kernel_launch(void* const* d_in, const int* in_sizes, int n_in,
                              void* d_out, int out_size)
{
    const float* hidden = (const float*)d_in[0];
    const float* Wqkv   = (const float*)d_in[1];
    const float* Wo     = (const float*)d_in[2];
    const float* qnw    = (const float*)d_in[3];
    const float* knw    = (const float*)d_in[4];
    const float* w0     = (const float*)d_in[5];
    const float* w1     = (const float*)d_in[6];
    const float* w2     = (const float*)d_in[7];
    const float* lrw    = (const float*)d_in[8];
    const float* lrb    = (const float*)d_in[9];
    const float* qksc   = (const float*)d_in[10];
    const float* qkof   = (const float*)d_in[11];
    const float* tttw   = (const float*)d_in[12];
    float* out = (float*)d_out;

    float *qkv, *lrpre, *lr, *pw02, *pw1, *gh, *dh, *ttt, *sum;
    GSYM(qkv, g_qkv);   GSYM(lrpre, g_lrpre); GSYM(lr, g_lr);
    GSYM(pw02, g_w02);  GSYM(pw1, g_w1);
    GSYM(gh, g_gh);     GSYM(dh, g_dh);
    GSYM(ttt, g_ttt);   GSYM(sum, g_sum);

    float *hxt,*wqt,*wot,*fqt,*fkt,*fvt,*w02t,*w1t,*dgpt,*vlt,*htt,*hnt,*smt;
    GSYM(hxt, g_hx_t); GSYM(wqt, g_wq_t); GSYM(wot, g_wo_t);
    GSYM(fqt, g_fq_t); GSYM(fkt, g_fk_t); GSYM(fvt, g_fv_t);
    GSYM(w02t, g_w02_t); GSYM(w1t, g_w1_t);
    GSYM(dgpt, g_dgp_t); GSYM(vlt, g_vl_t); GSYM(htt, g_ht_t);
    GSYM(hnt, g_hn_t); GSYM(smt, g_sm_t);

    __nv_bfloat16 *aqh,*aql,*akh,*akl,*avh,*avl;
    GSYM(aqh, g_aq_h); GSYM(aql, g_aq_l); GSYM(akh, g_ak_h); GSYM(akl, g_ak_l);
    GSYM(avh, g_av_h); GSYM(avl, g_av_l);

    // stage sizes: NT 55296*3=165888, NN (36864+17408)*3=162816, TN (33792+17408)*3=153600
    cudaFuncSetAttribute(tf_nt, cudaFuncAttributeMaxDynamicSharedMemorySize, 165888);
    cudaFuncSetAttribute(tf_pack_fwd, cudaFuncAttributeMaxDynamicSharedMemorySize, 165888);
    cudaFuncSetAttribute(tf_pack_upd, cudaFuncAttributeMaxDynamicSharedMemorySize, 153600);
    cudaFuncSetAttribute(tf_pack3, cudaFuncAttributeMaxDynamicSharedMemorySize, 165888);
    cudaFuncSetAttribute(attn_mma, cudaFuncAttributeMaxDynamicSharedMemorySize, ATTN_SMEM);

    cvt_tf<<<8192, 256>>>(hidden, hxt, (long)4096 * 2048);
    cvt_tf<<<12288, 256>>>(Wqkv, wqt, (long)6144 * 2048);
    cvt_tf<<<4096, 256>>>(Wo, wot, (long)2048 * 2048);

    {
        GP p{hxt, wqt, qkv, nullptr, 4096, 6144, 2048, 2048, 2048, 0, 0, 0, 48, 16};
        tf_nt<<<dim3(48, 16, 1), 256, 165888>>>(p);
    }
    lr_gemm<<<2048, 256>>>(hidden, lrw, lrpre);

    float base = (float)(0.001 + log(-expm1(-0.001)));
    prep_kernel<<<4096, 256>>>(qkv, lrpre, qnw, knw, qksc, qkof, lrb, base,
                               aqh, aql, akh, akl, avh, avl,
                               fqt, fkt, fvt, lr);
    attn_mma<<<dim3(32, 16, 2), 128, ATTN_SMEM>>>(aqh, aql, akh, akl, avh, avl, sum);

    copyw<<<16384, 256>>>(w0, w1, w2, pw02, w02t, pw1, w1t);

    long sSeq = (long)SEQ * FDM;
    long sChk = (long)1024 * FDM;
    long sW   = (long)FDM * FDM;
    long sW02 = (long)1024 * FDM;
    long sGH  = (long)1024 * 1024;

    // ---- chunk 0 ----
    {
        GP p1{fkt, w02t, gh, nullptr, 1024, 1024, 512, 512, 512, sSeq, sW02, sGH, 8, 4};
        GP p2{fvt, w1t, dh, nullptr, 1024, 512, 512, 512, 512, sSeq, sW, sChk, 4, 4};
        tf_pack_fwd<<<dim3(8, 4, 16), 256, 165888>>>(p1, p2, 8);
    }
    elem2<<<16384, 256>>>(fvt, lr, gh, dh, dgpt, vlt, htt, 0);
    {
        GP p1{dgpt, fkt, pw02, w02t, 1024, 512, 1024, 1024, 512, sGH, sSeq, sW02, 4, 4};
        GP p2{vlt, htt, pw1, w1t, 512, 512, 1024, 512, 512, sChk, sChk, sW, 4, 2};
        tf_pack_upd<<<dim3(4, 4, 16), 256, 153600>>>(p1, p2, 8);
    }
    {
        GP p{fqt, w02t, gh, nullptr, 1024, 1024, 512, 512, 512, sSeq, sW02, sGH, 8, 4};
        tf_nt<<<dim3(8, 4, 8), 256, 165888>>>(p);
    }
    elem3<<<16384, 256>>>(gh, hnt);

    long co1 = (long)1024 * FDM;
    // ---- final(ck0) || fwd(ck1) packed ----
    {
        GP p1{hnt, w1t, ttt, nullptr, 1024, 512, 512, 512, 512, sChk, sW, sSeq, 4, 4};
        GP p2{fkt + co1, w02t, gh, nullptr, 1024, 1024, 512, 512, 512, sSeq, sW02, sGH, 8, 4};
        GP p3{fvt + co1, w1t, dh, nullptr, 1024, 512, 512, 512, 512, sSeq, sW, sChk, 4, 4};
        tf_pack3<<<dim3(8, 4, 24), 256, 165888>>>(p1, p2, p3, 8, 8);
    }
    // ---- chunk 1 ----
    elem2<<<16384, 256>>>(fvt, lr, gh, dh, dgpt, vlt, htt, 1024);
    {
        GP p1{dgpt, fkt + co1, pw02, w02t, 1024, 512, 1024, 1024, 512, sGH, sSeq, sW02, 4, 4};
        GP p2{vlt, htt, pw1, w1t, 512, 512, 1024, 512, 512, sChk, sChk, sW, 4, 2};
        tf_pack_upd<<<dim3(4, 4, 16), 256, 153600>>>(p1, p2, 8);
    }
    {
        GP p{fqt + co1, w02t, gh, nullptr, 1024, 1024, 512, 512, 512, sSeq, sW02, sGH, 8, 4};
        tf_nt<<<dim3(8, 4, 8), 256, 165888>>>(p);
    }
    elem3<<<16384, 256>>>(gh, hnt);
    {
        GP p{hnt, w1t, ttt + co1, nullptr, 1024, 512, 512, 512, 512, sChk, sW, sSeq, 4, 4};
        tf_nt<<<dim3(4, 4, 8), 256, 165888>>>(p);
    }

    post_kernel<<<dim3(4, 4096), 128>>>(ttt, tttw, sum, smt);
    {
        GP p{smt, wot, out, nullptr, 4096, 2048, 2048, 2048, 2048, 0, 0, 0, 16, 16};
        tf_nt<<<dim3(16, 16, 1), 256, 165888>>>(p);
    }
}

// round 15
// speedup vs baseline: 1.0268x; 1.0268x over previous
#include <cuda_runtime.h>
#include <cuda_bf16.h>
#include <cstdint>
#include <math.h>

#define SEQ 2048
#define DIMD 2048
#define FDM 512

// ------------------------- fp32 scratch (device globals) --------------------
__device__ float g_qkv [(size_t)4096 * 6144];
__device__ float g_lrpre[(size_t)4096 * 12];
__device__ float g_lr  [(size_t)4096 * 12];
__device__ float g_w02 [(size_t)8 * 1024 * FDM];
__device__ float g_w1  [(size_t)8 * FDM * FDM];
__device__ float g_gh  [(size_t)8 * 1024 * 1024];
__device__ float g_dh  [(size_t)8 * 1024 * FDM];
__device__ float g_ttt [(size_t)8 * SEQ * FDM];
__device__ float g_sum [(size_t)4096 * 2048];

// ---------------------- tf32 (pre-rounded fp32) operands --------------------
__device__ float g_hx_t [(size_t)4096 * 2048];
__device__ float g_wq_t [(size_t)6144 * 2048];
__device__ float g_wo_t [(size_t)2048 * 2048];
__device__ float g_fq_t [(size_t)8 * SEQ * FDM];
__device__ float g_fk_t [(size_t)8 * SEQ * FDM];
__device__ float g_fv_t [(size_t)8 * SEQ * FDM];
__device__ float g_w02_t[(size_t)8 * 1024 * FDM];
__device__ float g_w1_t [(size_t)8 * FDM * FDM];
__device__ float g_dgp_t[(size_t)8 * 1024 * 1024];
__device__ float g_vl_t [(size_t)8 * 1024 * FDM];
__device__ float g_ht_t [(size_t)8 * 1024 * FDM];
__device__ float g_hn_t [(size_t)8 * 1024 * FDM];
__device__ float g_sm_t [(size_t)4096 * 2048];

// ------------------- bf16 hi/lo (attention only) ----------------------------
__device__ __nv_bfloat16 g_aq_h[(size_t)4096*2048], g_aq_l[(size_t)4096*2048];
__device__ __nv_bfloat16 g_ak_h[(size_t)4096*2048], g_ak_l[(size_t)4096*2048];
__device__ __nv_bfloat16 g_av_h[(size_t)4096*2048], g_av_l[(size_t)4096*2048];

// ------------------------------ helpers -------------------------------------
__device__ __forceinline__ uint32_t smem_u32(const void* p) {
    uint32_t a;
    asm("{ .reg .u64 t; cvta.to.shared.u64 t, %1; cvt.u32.u64 %0, t; }" : "=r"(a) : "l"(p));
    return a;
}
__device__ __forceinline__ void cpa16(uint32_t s, const void* g) {
    asm volatile("cp.async.cg.shared.global [%0], [%1], 16;" :: "r"(s), "l"(g));
}
#define CP_COMMIT() asm volatile("cp.async.commit_group;" ::: "memory")
#define MMA16816(d, a, b0, b1) \
    asm volatile("mma.sync.aligned.m16n8k16.row.col.f32.bf16.bf16.f32 " \
        "{%0,%1,%2,%3}, {%4,%5,%6,%7}, {%8,%9}, {%0,%1,%2,%3};" \
        : "+f"((d)[0]), "+f"((d)[1]), "+f"((d)[2]), "+f"((d)[3]) \
        : "r"((a)[0]), "r"((a)[1]), "r"((a)[2]), "r"((a)[3]), "r"(b0), "r"(b1))
#define MMATF(d, a, b0, b1) \
    asm volatile("mma.sync.aligned.m16n8k8.row.col.f32.tf32.tf32.f32 " \
        "{%0,%1,%2,%3}, {%4,%5,%6,%7}, {%8,%9}, {%0,%1,%2,%3};" \
        : "+f"((d)[0]), "+f"((d)[1]), "+f"((d)[2]), "+f"((d)[3]) \
        : "r"((a)[0]), "r"((a)[1]), "r"((a)[2]), "r"((a)[3]), "r"(b0), "r"(b1))
__device__ __forceinline__ void ldmx4(uint32_t* r, uint32_t addr) {
    asm volatile("ldmatrix.sync.aligned.m8n8.x4.shared.b16 {%0,%1,%2,%3}, [%4];"
        : "=r"(r[0]), "=r"(r[1]), "=r"(r[2]), "=r"(r[3]) : "r"(addr));
}
__device__ __forceinline__ void ldmx4t(uint32_t* r, uint32_t addr) {
    asm volatile("ldmatrix.sync.aligned.m8n8.x4.trans.shared.b16 {%0,%1,%2,%3}, [%4];"
        : "=r"(r[0]), "=r"(r[1]), "=r"(r[2]), "=r"(r[3]) : "r"(addr));
}
__device__ __forceinline__ void split_w(float v, __nv_bfloat16* h, __nv_bfloat16* l, long i) {
    __nv_bfloat16 hv = __float2bfloat16_rn(v);
    h[i] = hv;
    l[i] = __float2bfloat16_rn(v - __bfloat162float(hv));
}
__device__ __forceinline__ float to_tf32(float v) {
    uint32_t u;
    asm("cvt.rna.tf32.f32 %0, %1;" : "=r"(u) : "f"(v));
    return __uint_as_float(u);
}
__device__ __forceinline__ uint32_t lds_u32(uint32_t addr) {
    uint32_t v;
    asm volatile("ld.shared.b32 %0, [%1];" : "=r"(v) : "r"(addr));
    return v;
}
__device__ __forceinline__ uint32_t pack_bf2(float a, float b) {
    __nv_bfloat162 t;
    t.x = __float2bfloat16_rn(a);
    t.y = __float2bfloat16_rn(b);
    return *(uint32_t*)&t;
}

// -------------------- TF32 mma.sync batched GEMM (3-stage) ------------------
struct GP {
    const float* A; const float* B;
    float* C; float* Ct;
    int M, N, K, lda, ldb;
    long sA, sB, sC;
    int gx, gy;
};

// tile: 128x128, 8 warps (wm 0..1 x wn 0..3), warp tile 64x32
template<int AT, int BT, bool ACC, bool SPLIT>
__device__ __forceinline__ void gemm_body(const GP p, int bz)
{
    if ((int)blockIdx.x >= p.gx || (int)blockIdx.y >= p.gy) return;
    constexpr int SA = AT ? 17408 : 18432;
    constexpr int SB = BT ? 17408 : 18432;
    constexpr int STAGE = SA + SB;
    extern __shared__ char smem[];
    uint32_t sb = smem_u32(smem);
    int tid = threadIdx.x, lane = tid & 31, wid = tid >> 5;
    int wm = wid >> 2, wn = wid & 3;
    const float* a = p.A + (long)bz * p.sA;
    const float* b = p.B + (long)bz * p.sB;
    int m0 = blockIdx.y << 7, n0 = blockIdx.x << 7;
    int lda = p.lda, ldb = p.ldb;

    float acc[4][4][4];
    #pragma unroll
    for (int i = 0; i < 4; ++i)
        #pragma unroll
        for (int j = 0; j < 4; ++j)
            #pragma unroll
            for (int q = 0; q < 4; ++q) acc[i][j][q] = 0.f;

    int Lm = lane >> 3, Lr = lane & 7;
    uint32_t aoff = (uint32_t)(((Lm & 1) * 8 + Lr) * 144 + (Lm >> 1) * 16);
    uint32_t boff = (uint32_t)(((Lm >> 1) * 8 + Lr) * 144 + (Lm & 1) * 16);

    auto issue = [&](int buf, int k0) {
        uint32_t st = sb + buf * STAGE;
        #pragma unroll
        for (int j = 0; j < 4; ++j) {
            int u = tid + j * 256;
            uint32_t so; long g;
            if (AT == 0) { int r = u >> 3, s = u & 7;  so = r * 144 + s * 16;
                           g = (long)(m0 + r) * lda + k0 + s * 4; }
            else         { int r = u >> 5, s = u & 31; so = r * 544 + s * 16;
                           g = (long)(k0 + r) * lda + m0 + s * 4; }
            cpa16(st + so, a + g);
            if (BT == 0) { int r = u >> 3, s = u & 7;  so = r * 144 + s * 16;
                           g = (long)(n0 + r) * ldb + k0 + s * 4; }
            else         { int r = u >> 5, s = u & 31; so = r * 544 + s * 16;
                           g = (long)(k0 + r) * ldb + n0 + s * 4; }
            cpa16(st + SA + so, b + g);
        }
        CP_COMMIT();
    };

    const int n = p.K >> 5;
    issue(0, 0);
    if (n > 1) issue(1, 32);
    int buf = 0;
    for (int i = 0; i < n; ++i) {
        if (i + 1 < n) asm volatile("cp.async.wait_group 1;" ::: "memory");
        else           asm volatile("cp.async.wait_group 0;" ::: "memory");
        __syncthreads();
        if (i + 2 < n) issue((i + 2) % 3, (i + 2) * 32);
        uint32_t st = sb + buf * STAGE;
        uint32_t stB = st + SA;
        #pragma unroll
        for (int kk = 0; kk < 32; kk += 8) {
            uint32_t af[4][4];
            #pragma unroll
            for (int mt = 0; mt < 4; ++mt) {
                if (AT == 0) {
                    ldmx4(af[mt], st + (wm * 64 + mt * 16) * 144 + kk * 4 + aoff);
                } else {
                    uint32_t ra = st + (kk + (lane & 3)) * 544
                                + (wm * 64 + mt * 16 + (lane >> 2)) * 4;
                    af[mt][0] = lds_u32(ra);
                    af[mt][1] = lds_u32(ra + 32);
                    af[mt][2] = lds_u32(ra + 4 * 544);
                    af[mt][3] = lds_u32(ra + 4 * 544 + 32);
                }
            }
            uint32_t bf_[4][2];
            if (BT == 0) {
                #pragma unroll
                for (int pp = 0; pp < 2; ++pp) {
                    uint32_t r4[4];
                    ldmx4(r4, stB + (wn * 32 + pp * 16) * 144 + kk * 4 + boff);
                    bf_[pp * 2 + 0][0] = r4[0]; bf_[pp * 2 + 0][1] = r4[1];
                    bf_[pp * 2 + 1][0] = r4[2]; bf_[pp * 2 + 1][1] = r4[3];
                }
            } else {
                #pragma unroll
                for (int nt = 0; nt < 4; ++nt) {
                    uint32_t rb = stB + (kk + (lane & 3)) * 544
                                + (wn * 32 + nt * 8 + (lane >> 2)) * 4;
                    bf_[nt][0] = lds_u32(rb);
                    bf_[nt][1] = lds_u32(rb + 4 * 544);
                }
            }
            #pragma unroll
            for (int nt = 0; nt < 4; ++nt)
                #pragma unroll
                for (int mt = 0; mt < 4; ++mt)
                    MMATF(acc[mt][nt], af[mt], bf_[nt][0], bf_[nt][1]);
        }
        buf = (buf == 2) ? 0 : buf + 1;
    }
    float* c = p.C + (long)bz * p.sC;
    float* ct = SPLIT ? p.Ct + (long)bz * p.sC : nullptr;
    int N = p.N;
    #pragma unroll
    for (int mt = 0; mt < 4; ++mt) {
        #pragma unroll
        for (int nt = 0; nt < 4; ++nt) {
            long r0 = m0 + wm * 64 + mt * 16 + (lane >> 2);
            int  cc = n0 + wn * 32 + nt * 8 + (lane & 3) * 2;
            long o0 = r0 * (long)N + cc;
            long o1 = (r0 + 8) * (long)N + cc;
            float v00 = acc[mt][nt][0], v01 = acc[mt][nt][1];
            float v10 = acc[mt][nt][2], v11 = acc[mt][nt][3];
            if (ACC) {
                float2 t0 = *(float2*)(c + o0), t1 = *(float2*)(c + o1);
                v00 += t0.x; v01 += t0.y; v10 += t1.x; v11 += t1.y;
            }
            *(float2*)(c + o0) = make_float2(v00, v01);
            *(float2*)(c + o1) = make_float2(v10, v11);
            if (SPLIT) {
                *(float2*)(ct + o0) = make_float2(to_tf32(v00), to_tf32(v01));
                *(float2*)(ct + o1) = make_float2(to_tf32(v10), to_tf32(v11));
            }
        }
    }
}

__global__ void __launch_bounds__(256, 2) tf_nt(GP p) {
    gemm_body<0, 0, false, false>(p, blockIdx.z);
}
__global__ void __launch_bounds__(256, 2) tf_pack_fwd(GP p1, GP p2, int z1) {
    if ((int)blockIdx.z < z1) gemm_body<0, 0, false, false>(p1, blockIdx.z);
    else                      gemm_body<0, 1, false, false>(p2, blockIdx.z - z1);
}
__global__ void __launch_bounds__(256, 2) tf_pack_upd(GP p1, GP p2, int z1) {
    if ((int)blockIdx.z < z1) gemm_body<1, 1, true, true>(p1, blockIdx.z);
    else                      gemm_body<1, 1, true, true>(p2, blockIdx.z - z1);
}
__global__ void __launch_bounds__(256, 2) tf_pack3(GP p1, GP p2, GP p3, int z1, int z2) {
    int z = blockIdx.z;
    if (z < z1)            gemm_body<0, 0, false, false>(p1, z);
    else if (z < z1 + z2)  gemm_body<0, 0, false, false>(p2, z - z1);
    else                   gemm_body<0, 1, false, false>(p3, z - z1 - z2);
}

// ------------------------ conversion kernel ---------------------------------
__global__ void cvt_tf(const float* __restrict__ x, float* __restrict__ o, long n)
{
    long i = ((long)blockIdx.x * 256 + threadIdx.x) * 4;
    if (i >= n) return;
    float4 v = *(const float4*)(x + i);
    float4 w;
    w.x = to_tf32(v.x); w.y = to_tf32(v.y); w.z = to_tf32(v.z); w.w = to_tf32(v.w);
    *(float4*)(o + i) = w;
}

// ---------------- small SGEMM for the N=12 lr GEMM --------------------------
__global__ void lr_gemm(const float* __restrict__ A, const float* __restrict__ B,
                        float* __restrict__ C)
{
    __shared__ float bs[12][128];
    int row = blockIdx.x * 2 + (threadIdx.x >> 7);
    int tid = threadIdx.x & 127;
    float acc[12];
    #pragma unroll
    for (int c = 0; c < 12; ++c) acc[c] = 0.f;
    for (int k0 = 0; k0 < 2048; k0 += 128) {
        if (threadIdx.x < 128)
            #pragma unroll
            for (int c = 0; c < 12; ++c) bs[c][tid] = B[c * 2048 + k0 + tid];
        __syncthreads();
        float a = A[(long)row * 2048 + k0 + tid];
        #pragma unroll
        for (int c = 0; c < 12; ++c) acc[c] += a * bs[c][tid];
        __syncthreads();
    }
    __shared__ float red[2][12][4];
    #pragma unroll
    for (int c = 0; c < 12; ++c) {
        float v = acc[c];
        #pragma unroll
        for (int o = 16; o > 0; o >>= 1) v += __shfl_down_sync(0xffffffffu, v, o);
        if ((tid & 31) == 0) red[threadIdx.x >> 7][c][tid >> 5] = v;
    }
    __syncthreads();
    if (tid < 12) {
        int w = threadIdx.x >> 7;
        C[(long)row * 12 + tid] = red[w][tid][0] + red[w][tid][1] + red[w][tid][2] + red[w][tid][3];
    }
}

// ------------------------- block reduce (256 thr) ---------------------------
__device__ __forceinline__ float blockReduceSum(float v, float* sred)
{
    int lane = threadIdx.x & 31;
    #pragma unroll
    for (int o = 16; o > 0; o >>= 1) v += __shfl_down_sync(0xffffffffu, v, o);
    if (lane == 0) sred[threadIdx.x >> 5] = v;
    __syncthreads();
    if (threadIdx.x < 8) {
        float r = sred[threadIdx.x];
        #pragma unroll
        for (int o = 4; o > 0; o >>= 1) r += __shfl_down_sync(0xffu, r, o);
        if (threadIdx.x == 0) sred[0] = r;
    }
    __syncthreads();
    float out = sred[0];
    __syncthreads();
    return out;
}

// --------- prep: rmsnorm+rope + silu/L2 + lr ---------------------------------
__global__ void prep_kernel(const float* __restrict__ qkv, const float* __restrict__ lrpre,
                            const float* __restrict__ qnw, const float* __restrict__ knw,
                            const float* __restrict__ qksc, const float* __restrict__ qkof,
                            const float* __restrict__ lrb, float base_lr_inv,
                            __nv_bfloat16* __restrict__ aqh, __nv_bfloat16* __restrict__ aql,
                            __nv_bfloat16* __restrict__ akh, __nv_bfloat16* __restrict__ akl,
                            __nv_bfloat16* __restrict__ avh, __nv_bfloat16* __restrict__ avl,
                            float* __restrict__ fqt, float* __restrict__ fkt,
                            float* __restrict__ fvt, float* __restrict__ lrout)
{
    __shared__ float s_q[2048];
    __shared__ float s_k[2048];
    __shared__ float sred[8];
    int row = blockIdx.x;
    int b = row >> 11, t = row & 2047;
    int tid = threadIdx.x;
    const float* qr = qkv + (long)row * 6144;
    const float* kr = qr + 2048;
    const float* vr = qr + 4096;
    const float qscale = 0.088388347648318447f * 1.4426950408889634f;

    float qv[8], kv[8], fqv[8], fkv[8], fvv[8];
    float sq = 0.f, sk = 0.f;
    float p2q[4] = {0, 0, 0, 0}, p2k[4] = {0, 0, 0, 0};
    #pragma unroll
    for (int j = 0; j < 8; ++j) {
        int i = j * 256 + tid;
        float q = qr[i], k = kr[i], v = vr[i];
        qv[j] = q; kv[j] = k;
        sq += q * q; sk += k * k;
        float fqe = (q / (1.f + expf(-q))) * qksc[i * 2 + 0] + qkof[i * 2 + 0];
        float fke = (k / (1.f + expf(-k))) * qksc[i * 2 + 1] + qkof[i * 2 + 1];
        fqv[j] = fqe; fkv[j] = fke; fvv[j] = v / (1.f + expf(-v));
        p2q[j >> 1] += fqe * fqe;
        p2k[j >> 1] += fke * fke;
        split_w(v, avh, avl, (long)row * DIMD + i);
    }
    float SQ = blockReduceSum(sq, sred);
    float SK = blockReduceSum(sk, sred);
    float G2Q[4], G2K[4];
    #pragma unroll
    for (int g = 0; g < 4; ++g) G2Q[g] = blockReduceSum(p2q[g], sred);
    #pragma unroll
    for (int g = 0; g < 4; ++g) G2K[g] = blockReduceSum(p2k[g], sred);
    float rq = rsqrtf(SQ * (1.f / 2048.f) + 1e-6f);
    float rk = rsqrtf(SK * (1.f / 2048.f) + 1e-6f);
    #pragma unroll
    for (int j = 0; j < 8; ++j) {
        int i = j * 256 + tid;
        s_q[i] = qv[j] * rq * qnw[i];
        s_k[i] = kv[j] * rk * knw[i];
        int g = j >> 1;
        long fb = (((long)(b * 4 + g)) * SEQ + t) * FDM + (i & 511);
        fqt[fb] = to_tf32(fqv[j] / (sqrtf(G2Q[g]) + 1e-12f));
        fkt[fb] = to_tf32(fkv[j] / (sqrtf(G2K[g]) + 1e-12f));
        fvt[fb] = to_tf32(fvv[j]);
    }
    __syncthreads();
    #pragma unroll
    for (int j = 0; j < 8; ++j) {
        int i = j * 256 + tid;
        int pos = i & 127;
        int fi = pos & 63;
        float invf = expf(-(float)fi * (logf(500000.f) / 64.f));
        float sn, cs;
        sincosf((float)t * invf, &sn, &cs);
        float oq, ok_;
        if (pos < 64) {
            oq  = s_q[i] * cs - s_q[i + 64] * sn;
            ok_ = s_k[i] * cs - s_k[i + 64] * sn;
        } else {
            oq  = s_q[i] * cs + s_q[i - 64] * sn;
            ok_ = s_k[i] * cs + s_k[i - 64] * sn;
        }
        split_w(oq * qscale, aqh, aql, (long)row * DIMD + i);
        split_w(ok_, akh, akl, (long)row * DIMD + i);
    }
    if (tid < 12) {
        float x = lrpre[(long)row * 12 + tid] + lrb[tid] + base_lr_inv;
        lrout[(long)row * 12 + tid] = (x > 20.f) ? x : log1pf(expf(x));
    }
}

// ------------- HMMA flash attention, register softmax (4 warps) --------------
#define ATS 272
#define O_QH 0
#define O_QL 17408
#define O_KH 34816
#define O_KL 52224
#define O_VH 69632
#define O_VL 87040
#define ATTN_SMEM 104448

__global__ void __launch_bounds__(128, 2)
attn_mma(const __nv_bfloat16* __restrict__ Qh, const __nv_bfloat16* __restrict__ Ql,
         const __nv_bfloat16* __restrict__ Kh, const __nv_bfloat16* __restrict__ Kl,
         const __nv_bfloat16* __restrict__ Vh, const __nv_bfloat16* __restrict__ Vl,
         float* __restrict__ O)
{
    extern __shared__ char smc[];
    uint32_t sb = smem_u32(smc);
    int tid = threadIdx.x, lane = tid & 31, wid = tid >> 5;
    int q0 = blockIdx.x << 6, h = blockIdx.y, b = blockIdx.z;
    int wr = wid * 16;
    uint32_t a_row = (lane & 7) + ((lane >> 3) & 1) * 8;
    uint32_t a_kb  = ((lane >> 4) & 1) * 16;
    uint32_t b_row = (lane & 7) + ((lane >> 4) & 1) * 8;
    uint32_t b_kb  = ((lane >> 3) & 1) * 16;
    uint32_t b_kr  = (lane & 7) + ((lane >> 3) & 1) * 8;
    uint32_t b_no  = ((lane >> 4) & 1) * 8;

    #pragma unroll
    for (int j = 0; j < 8; ++j) {
        int u = tid + j * 128;
        int r = u >> 4, s = u & 15;
        long g = ((long)(b * SEQ + q0 + r)) * DIMD + h * 128 + s * 8;
        cpa16(sb + O_QH + r * ATS + s * 16, Qh + g);
        cpa16(sb + O_QL + r * ATS + s * 16, Ql + g);
    }
    CP_COMMIT();

    float oacc[16][4];
    #pragma unroll
    for (int i = 0; i < 16; ++i)
        #pragma unroll
        for (int q = 0; q < 4; ++q) oacc[i][q] = 0.f;
    float m_lo = -INFINITY, m_hi = -INFINITY, l_lo = 0.f, l_hi = 0.f;

    int r_lo = q0 + wr + (lane >> 2);
    int r_hi = r_lo + 8;

    int kt_hi2 = q0 >> 6;
    int kt_lo2 = (q0 >= 1024) ? ((q0 - 1023) >> 6) : 0;
    for (int kt = kt_lo2; kt <= kt_hi2; ++kt) {
        int j0 = kt << 6;
        __syncthreads();
        #pragma unroll
        for (int j = 0; j < 8; ++j) {
            int u = tid + j * 128;
            int r = u >> 4, s = u & 15;
            long g = ((long)(b * SEQ + j0 + r)) * DIMD + h * 128 + s * 8;
            uint32_t so = r * ATS + s * 16;
            cpa16(sb + O_KH + so, Kh + g);
            cpa16(sb + O_KL + so, Kl + g);
            cpa16(sb + O_VH + so, Vh + g);
            cpa16(sb + O_VL + so, Vl + g);
        }
        CP_COMMIT();
        asm volatile("cp.async.wait_group 0;" ::: "memory");
        __syncthreads();

        float sacc[8][4];
        #pragma unroll
        for (int i = 0; i < 8; ++i)
            #pragma unroll
            for (int q = 0; q < 4; ++q) sacc[i][q] = 0.f;
        #pragma unroll
        for (int kk = 0; kk < 8; ++kk) {
            uint32_t ah4[4], al4[4];
            uint32_t ra = sb + O_QH + (wr + a_row) * ATS + kk * 32 + a_kb;
            ldmx4(ah4, ra);
            ldmx4(al4, ra + (O_QL - O_QH));
            uint32_t bh4[4][4], bl4[4][4];
            #pragma unroll
            for (int p = 0; p < 4; ++p) {
                uint32_t rb = sb + O_KH + (p * 16 + b_row) * ATS + kk * 32 + b_kb;
                ldmx4(bh4[p], rb);
                ldmx4(bl4[p], rb + (O_KL - O_KH));
            }
            #pragma unroll
            for (int nt = 0; nt < 8; ++nt) {
                uint32_t b0h = bh4[nt >> 1][(nt & 1) * 2 + 0];
                uint32_t b1h = bh4[nt >> 1][(nt & 1) * 2 + 1];
                uint32_t b0l = bl4[nt >> 1][(nt & 1) * 2 + 0];
                uint32_t b1l = bl4[nt >> 1][(nt & 1) * 2 + 1];
                MMA16816(sacc[nt], ah4, b0h, b1h);
                MMA16816(sacc[nt], ah4, b0l, b1l);
                MMA16816(sacc[nt], al4, b0h, b1h);
            }
        }
        float tmax_lo = -INFINITY, tmax_hi = -INFINITY;
        #pragma unroll
        for (int nt = 0; nt < 8; ++nt) {
            #pragma unroll
            for (int e = 0; e < 2; ++e) {
                int col = j0 + nt * 8 + (lane & 3) * 2 + e;
                bool ok0 = (col <= r_lo) && (r_lo - col < 1024);
                bool ok1 = (col <= r_hi) && (r_hi - col < 1024);
                sacc[nt][e]     = ok0 ? sacc[nt][e]     : -INFINITY;
                sacc[nt][2 + e] = ok1 ? sacc[nt][2 + e] : -INFINITY;
                tmax_lo = fmaxf(tmax_lo, sacc[nt][e]);
                tmax_hi = fmaxf(tmax_hi, sacc[nt][2 + e]);
            }
        }
        tmax_lo = fmaxf(tmax_lo, __shfl_xor_sync(0xffffffffu, tmax_lo, 1));
        tmax_lo = fmaxf(tmax_lo, __shfl_xor_sync(0xffffffffu, tmax_lo, 2));
        tmax_hi = fmaxf(tmax_hi, __shfl_xor_sync(0xffffffffu, tmax_hi, 1));
        tmax_hi = fmaxf(tmax_hi, __shfl_xor_sync(0xffffffffu, tmax_hi, 2));
        float mt_lo = fmaxf(m_lo, tmax_lo);
        float mt_hi = fmaxf(m_hi, tmax_hi);
        float mte_lo = (mt_lo > -INFINITY) ? mt_lo : 0.f;
        float mte_hi = (mt_hi > -INFINITY) ? mt_hi : 0.f;
        float corr_lo = exp2f(m_lo - mte_lo);
        float corr_hi = exp2f(m_hi - mte_hi);

        uint32_t ph[4][4], pl[4][4];
        float ls_lo = 0.f, ls_hi = 0.f;
        #pragma unroll
        for (int k2 = 0; k2 < 4; ++k2) {
            #pragma unroll
            for (int half = 0; half < 2; ++half) {
                int nt = k2 * 2 + half;
                float p00 = exp2f(sacc[nt][0] - mte_lo);
                float p01 = exp2f(sacc[nt][1] - mte_lo);
                float p10 = exp2f(sacc[nt][2] - mte_hi);
                float p11 = exp2f(sacc[nt][3] - mte_hi);
                ls_lo += p00 + p01;
                ls_hi += p10 + p11;
                uint32_t h0 = pack_bf2(p00, p01);
                uint32_t h1 = pack_bf2(p10, p11);
                __nv_bfloat162 hb0 = *(__nv_bfloat162*)&h0;
                __nv_bfloat162 hb1 = *(__nv_bfloat162*)&h1;
                uint32_t l0 = pack_bf2(p00 - __bfloat162float(hb0.x),
                                       p01 - __bfloat162float(hb0.y));
                uint32_t l1 = pack_bf2(p10 - __bfloat162float(hb1.x),
                                       p11 - __bfloat162float(hb1.y));
                ph[k2][half * 2 + 0] = h0; ph[k2][half * 2 + 1] = h1;
                pl[k2][half * 2 + 0] = l0; pl[k2][half * 2 + 1] = l1;
            }
        }
        ls_lo += __shfl_xor_sync(0xffffffffu, ls_lo, 1);
        ls_lo += __shfl_xor_sync(0xffffffffu, ls_lo, 2);
        ls_hi += __shfl_xor_sync(0xffffffffu, ls_hi, 1);
        ls_hi += __shfl_xor_sync(0xffffffffu, ls_hi, 2);
        l_lo = l_lo * corr_lo + ls_lo;
        l_hi = l_hi * corr_hi + ls_hi;
        m_lo = mt_lo; m_hi = mt_hi;

        #pragma unroll
        for (int nt = 0; nt < 16; ++nt) {
            oacc[nt][0] *= corr_lo; oacc[nt][1] *= corr_lo;
            oacc[nt][2] *= corr_hi; oacc[nt][3] *= corr_hi;
        }
        #pragma unroll
        for (int k2 = 0; k2 < 4; ++k2) {
            #pragma unroll
            for (int p2 = 0; p2 < 8; ++p2) {
                uint32_t vh4[4], vl4[4];
                uint32_t rb = sb + O_VH + (k2 * 16 + b_kr) * ATS + (p2 * 16 + b_no) * 2;
                ldmx4t(vh4, rb);
                ldmx4t(vl4, rb + (O_VL - O_VH));
                #pragma unroll
                for (int sub = 0; sub < 2; ++sub) {
                    int nt = p2 * 2 + sub;
                    uint32_t b0h = vh4[sub * 2], b1h = vh4[sub * 2 + 1];
                    uint32_t b0l = vl4[sub * 2], b1l = vl4[sub * 2 + 1];
                    MMA16816(oacc[nt], ph[k2], b0h, b1h);
                    MMA16816(oacc[nt], ph[k2], b0l, b1l);
                    MMA16816(oacc[nt], pl[k2], b0h, b1h);
                }
            }
        }
    }
    float rl0 = 1.f / l_lo, rl1 = 1.f / l_hi;
    #pragma unroll
    for (int nt = 0; nt < 16; ++nt) {
        int col = nt * 8 + (lane & 3) * 2;
        long o0 = ((long)(b * SEQ + r_lo)) * 2048 + h * 128 + col;
        long o1 = ((long)(b * SEQ + r_hi)) * 2048 + h * 128 + col;
        *(float2*)(O + o0) = make_float2(oacc[nt][0] * rl0, oacc[nt][1] * rl0);
        *(float2*)(O + o1) = make_float2(oacc[nt][2] * rl1, oacc[nt][3] * rl1);
    }
}

// --------------------------- TTT helper kernels -----------------------------
__global__ void copyw(const float* __restrict__ w0, const float* __restrict__ w1,
                      const float* __restrict__ w2,
                      float* __restrict__ o02, float* __restrict__ o02t,
                      float* __restrict__ o1, float* __restrict__ o1t)
{
    long idx = (long)blockIdx.x * 256 + threadIdx.x;
    int col = idx & 511;
    int row = (idx >> 9) & 1023;
    int h = (idx >> 19) & 3;
    long src = (long)h * 262144 + (long)(row & 511) * 512 + col;
    float v = (row < 512) ? w0[src] : w2[src];
    o02[idx] = v;
    o02t[idx] = to_tf32(v);
    if (idx < (long)2 * 1024 * 1024) {
        float v1 = w1[idx & ((long)4 * 262144 - 1)];
        o1[idx] = v1;
        o1t[idx] = to_tf32(v1);
    }
}

__global__ void elem2(const float* __restrict__ fvt, const float* __restrict__ lr,
                      const float* __restrict__ gh, const float* __restrict__ dhin,
                      float* __restrict__ dgpt, float* __restrict__ vlt,
                      float* __restrict__ htt, int ck0)
{
    long idx = (long)blockIdx.x * 256 + threadIdx.x;
    int col = idx & 511;
    long tt = idx >> 9;
    int c = tt & 1023, bh = tt >> 10;
    int b = bh >> 2, h = bh & 3;
    long row = (long)b * SEQ + ck0 + c;
    float l0 = lr[row * 12 + h], l1 = lr[row * 12 + 4 + h], l2 = lr[row * 12 + 8 + h];
    long gi = (long)bh * 1048576 + (long)c * 1024 + col;
    float g = gh[gi], hp = gh[gi + 512], d = dhin[idx];
    float sig = 1.f / (1.f + expf(-g));
    float sg = g * sig;
    htt[idx] = to_tf32(sg * hp);
    float v = fvt[((long)bh * SEQ + ck0 + c) * FDM + col];
    dgpt[gi]       = to_tf32(d * hp * (sig * (1.f + g * (1.f - sig))) * l0);
    dgpt[gi + 512] = to_tf32(d * sg * l2);
    vlt[idx]       = to_tf32(v * l1);
}

__global__ void elem3(const float* __restrict__ gh, float* __restrict__ hnt)
{
    long idx = (long)blockIdx.x * 256 + threadIdx.x;
    int col = idx & 511;
    long tt = idx >> 9;
    int c = tt & 1023, bh = tt >> 10;
    long gi = (long)bh * 1048576 + (long)c * 1024 + col;
    float g = gh[gi];
    hnt[idx] = to_tf32((g / (1.f + expf(-g))) * gh[gi + 512]);
}

// -------------------- ttt rmsnorm + add attention result --------------------
__global__ void post_kernel(const float* __restrict__ ttt, const float* __restrict__ tw,
                            const float* __restrict__ sum, float* __restrict__ smt)
{
    __shared__ float sr[4];
    int fh = blockIdx.x, row = blockIdx.y;
    int b = row >> 11, t = row & 2047;
    int bh = b * 4 + fh;
    const float* src = ttt + ((long)bh * SEQ + t) * FDM;
    int tid = threadIdx.x;
    float v[4], ss = 0.f;
    #pragma unroll
    for (int j = 0; j < 4; ++j) { v[j] = src[tid + 128 * j]; ss += v[j] * v[j]; }
    #pragma unroll
    for (int o = 16; o > 0; o >>= 1) ss += __shfl_down_sync(0xffffffffu, ss, o);
    if ((tid & 31) == 0) sr[tid >> 5] = ss;
    __syncthreads();
    float tot = sr[0] + sr[1] + sr[2] + sr[3];
    float r = rsqrtf(tot * (1.f / 512.f) + 1e-6f);
    #pragma unroll
    for (int j = 0; j < 4; ++j) {
        int i = tid + 128 * j;
        long o = (long)row * 2048 + fh * 512 + i;
        smt[o] = to_tf32(sum[o] + v[j] * r * tw[i]);
    }
}

// --------------------------------- launch -----------------------------------
#define GSYM(p, s) cudaGetSymbolAddress((void**)&(p), s)

extern "C" void kernel_launch(void* const* d_in, const int* in_sizes, int n_in,
                              void* d_out, int out_size)
{
    const float* hidden = (const float*)d_in[0];
    const float* Wqkv   = (const float*)d_in[1];
    const float* Wo     = (const float*)d_in[2];
    const float* qnw    = (const float*)d_in[3];
    const float* knw    = (const float*)d_in[4];
    const float* w0     = (const float*)d_in[5];
    const float* w1     = (const float*)d_in[6];
    const float* w2     = (const float*)d_in[7];
    const float* lrw    = (const float*)d_in[8];
    const float* lrb    = (const float*)d_in[9];
    const float* qksc   = (const float*)d_in[10];
    const float* qkof   = (const float*)d_in[11];
    const float* tttw   = (const float*)d_in[12];
    float* out = (float*)d_out;

    float *qkv, *lrpre, *lr, *pw02, *pw1, *gh, *dh, *ttt, *sum;
    GSYM(qkv, g_qkv);   GSYM(lrpre, g_lrpre); GSYM(lr, g_lr);
    GSYM(pw02, g_w02);  GSYM(pw1, g_w1);
    GSYM(gh, g_gh);     GSYM(dh, g_dh);
    GSYM(ttt, g_ttt);   GSYM(sum, g_sum);

    float *hxt,*wqt,*wot,*fqt,*fkt,*fvt,*w02t,*w1t,*dgpt,*vlt,*htt,*hnt,*smt;
    GSYM(hxt, g_hx_t); GSYM(wqt, g_wq_t); GSYM(wot, g_wo_t);
    GSYM(fqt, g_fq_t); GSYM(fkt, g_fk_t); GSYM(fvt, g_fv_t);
    GSYM(w02t, g_w02_t); GSYM(w1t, g_w1_t);
    GSYM(dgpt, g_dgp_t); GSYM(vlt, g_vl_t); GSYM(htt, g_ht_t);
    GSYM(hnt, g_hn_t); GSYM(smt, g_sm_t);

    __nv_bfloat16 *aqh,*aql,*akh,*akl,*avh,*avl;
    GSYM(aqh, g_aq_h); GSYM(aql, g_aq_l); GSYM(akh, g_ak_h); GSYM(akl, g_ak_l);
    GSYM(avh, g_av_h); GSYM(avl, g_av_l);

    cudaFuncSetAttribute(tf_nt, cudaFuncAttributeMaxDynamicSharedMemorySize, 110592);
    cudaFuncSetAttribute(tf_pack_fwd, cudaFuncAttributeMaxDynamicSharedMemorySize, 110592);
    cudaFuncSetAttribute(tf_pack_upd, cudaFuncAttributeMaxDynamicSharedMemorySize, 104448);
    cudaFuncSetAttribute(tf_pack3, cudaFuncAttributeMaxDynamicSharedMemorySize, 110592);
    cudaFuncSetAttribute(attn_mma, cudaFuncAttributeMaxDynamicSharedMemorySize, ATTN_SMEM);

    cvt_tf<<<8192, 256>>>(hidden, hxt, (long)4096 * 2048);
    cvt_tf<<<12288, 256>>>(Wqkv, wqt, (long)6144 * 2048);
    cvt_tf<<<4096, 256>>>(Wo, wot, (long)2048 * 2048);

    {
        GP p{hxt, wqt, qkv, nullptr, 4096, 6144, 2048, 2048, 2048, 0, 0, 0, 48, 32};
        tf_nt<<<dim3(48, 32, 1), 256, 110592>>>(p);
    }
    lr_gemm<<<2048, 256>>>(hidden, lrw, lrpre);

    float base = (float)(0.001 + log(-expm1(-0.001)));
    prep_kernel<<<4096, 256>>>(qkv, lrpre, qnw, knw, qksc, qkof, lrb, base,
                               aqh, aql, akh, akl, avh, avl,
                               fqt, fkt, fvt, lr);
    attn_mma<<<dim3(32, 16, 2), 128, ATTN_SMEM>>>(aqh, aql, akh, akl, avh, avl, sum);

    copyw<<<16384, 256>>>(w0, w1, w2, pw02, w02t, pw1, w1t);

    long sSeq = (long)SEQ * FDM;
    long sChk = (long)1024 * FDM;
    long sW   = (long)FDM * FDM;
    long sW02 = (long)1024 * FDM;
    long sGH  = (long)1024 * 1024;

    // ---- chunk 0 ----
    {
        GP p1{fkt, w02t, gh, nullptr, 1024, 1024, 512, 512, 512, sSeq, sW02, sGH, 8, 8};
        GP p2{fvt, w1t, dh, nullptr, 1024, 512, 512, 512, 512, sSeq, sW, sChk, 4, 8};
        tf_pack_fwd<<<dim3(8, 8, 16), 256, 110592>>>(p1, p2, 8);
    }
    elem2<<<16384, 256>>>(fvt, lr, gh, dh, dgpt, vlt, htt, 0);
    {
        GP p1{dgpt, fkt, pw02, w02t, 1024, 512, 1024, 1024, 512, sGH, sSeq, sW02, 4, 8};
        GP p2{vlt, htt, pw1, w1t, 512, 512, 1024, 512, 512, sChk, sChk, sW, 4, 4};
        tf_pack_upd<<<dim3(4, 8, 16), 256, 104448>>>(p1, p2, 8);
    }
    {
        GP p{fqt, w02t, gh, nullptr, 1024, 1024, 512, 512, 512, sSeq, sW02, sGH, 8, 8};
        tf_nt<<<dim3(8, 8, 8), 256, 110592>>>(p);
    }
    elem3<<<16384, 256>>>(gh, hnt);

    long co1 = (long)1024 * FDM;
    // ---- final(ck0) || fwd(ck1) packed ----
    {
        GP p1{hnt, w1t, ttt, nullptr, 1024, 512, 512, 512, 512, sChk, sW, sSeq, 4, 8};
        GP p2{fkt + co1, w02t, gh, nullptr, 1024, 1024, 512, 512, 512, sSeq, sW02, sGH, 8, 8};
        GP p3{fvt + co1, w1t, dh, nullptr, 1024, 512, 512, 512, 512, sSeq, sW, sChk, 4, 8};
        tf_pack3<<<dim3(8, 8, 24), 256, 110592>>>(p1, p2, p3, 8, 8);
    }
    // ---- chunk 1 ----
    elem2<<<16384, 256>>>(fvt, lr, gh, dh, dgpt, vlt, htt, 1024);
    {
        GP p1{dgpt, fkt + co1, pw02, w02t, 1024, 512, 1024, 1024, 512, sGH, sSeq, sW02, 4, 8};
        GP p2{vlt, htt, pw1, w1t, 512, 512, 1024, 512, 512, sChk, sChk, sW, 4, 4};
        tf_pack_upd<<<dim3(4, 8, 16), 256, 104448>>>(p1, p2, 8);
    }
    {
        GP p{fqt + co1, w02t, gh, nullptr, 1024, 1024, 512, 512, 512, sSeq, sW02, sGH, 8, 8};
        tf_nt<<<dim3(8, 8, 8), 256, 110592>>>(p);
    }
    elem3<<<16384, 256>>>(gh, hnt);
    {
        GP p{hnt, w1t, ttt + co1, nullptr, 1024, 512, 512, 512, 512, sChk, sW, sSeq, 4, 8};
        tf_nt<<<dim3(4, 8, 8), 256, 110592>>>(p);
    }

    post_kernel<<<dim3(4, 4096), 128>>>(ttt, tttw, sum, smt);
    {
        GP p{smt, wot, out, nullptr, 4096, 2048, 2048, 2048, 2048, 0, 0, 0, 16, 32};
        tf_nt<<<dim3(16, 32, 1), 256, 110592>>>(p);
    }
}

// round 16
// speedup vs baseline: 1.0537x; 1.0262x over previous
#include <cuda_runtime.h>
#include <cuda_bf16.h>
#include <cstdint>
#include <math.h>

#define SEQ 2048
#define DIMD 2048
#define FDM 512

// ------------------------- fp32 scratch (device globals) --------------------
__device__ float g_qkv [(size_t)4096 * 6144];
__device__ float g_lrpre[(size_t)4096 * 12];
__device__ float g_lr  [(size_t)4096 * 12];
__device__ float g_w02 [(size_t)8 * 1024 * FDM];
__device__ float g_w1  [(size_t)8 * FDM * FDM];
__device__ float g_gh  [(size_t)8 * 1024 * 1024];
__device__ float g_dh  [(size_t)8 * 1024 * FDM];
__device__ float g_ttt [(size_t)8 * SEQ * FDM];
__device__ float g_sum [(size_t)4096 * 2048];

// ---------------------- tf32 (pre-rounded fp32) operands --------------------
__device__ float g_hx_t [(size_t)4096 * 2048];
__device__ float g_wq_t [(size_t)6144 * 2048];
__device__ float g_wo_t [(size_t)2048 * 2048];
__device__ float g_fq_t [(size_t)8 * SEQ * FDM];
__device__ float g_fk_t [(size_t)8 * SEQ * FDM];
__device__ float g_fv_t [(size_t)8 * SEQ * FDM];
__device__ float g_w02_t[(size_t)8 * 1024 * FDM];
__device__ float g_w1_t [(size_t)8 * FDM * FDM];
__device__ float g_dgp_t[(size_t)8 * 1024 * 1024];
__device__ float g_vl_t [(size_t)8 * 1024 * FDM];
__device__ float g_ht_t [(size_t)8 * 1024 * FDM];
__device__ float g_hn_t [(size_t)8 * 1024 * FDM];
__device__ float g_sm_t [(size_t)4096 * 2048];

// ------------------- bf16 hi/lo (attention only) ----------------------------
__device__ __nv_bfloat16 g_aq_h[(size_t)4096*2048], g_aq_l[(size_t)4096*2048];
__device__ __nv_bfloat16 g_ak_h[(size_t)4096*2048], g_ak_l[(size_t)4096*2048];
__device__ __nv_bfloat16 g_av_h[(size_t)4096*2048], g_av_l[(size_t)4096*2048];

// ------------------------------ helpers -------------------------------------
__device__ __forceinline__ uint32_t smem_u32(const void* p) {
    uint32_t a;
    asm("{ .reg .u64 t; cvta.to.shared.u64 t, %1; cvt.u32.u64 %0, t; }" : "=r"(a) : "l"(p));
    return a;
}
__device__ __forceinline__ void cpa16(uint32_t s, const void* g) {
    asm volatile("cp.async.cg.shared.global [%0], [%1], 16;" :: "r"(s), "l"(g));
}
#define CP_COMMIT() asm volatile("cp.async.commit_group;" ::: "memory")
#define MMA16816(d, a, b0, b1) \
    asm volatile("mma.sync.aligned.m16n8k16.row.col.f32.bf16.bf16.f32 " \
        "{%0,%1,%2,%3}, {%4,%5,%6,%7}, {%8,%9}, {%0,%1,%2,%3};" \
        : "+f"((d)[0]), "+f"((d)[1]), "+f"((d)[2]), "+f"((d)[3]) \
        : "r"((a)[0]), "r"((a)[1]), "r"((a)[2]), "r"((a)[3]), "r"(b0), "r"(b1))
#define MMATF(d, a, b0, b1) \
    asm volatile("mma.sync.aligned.m16n8k8.row.col.f32.tf32.tf32.f32 " \
        "{%0,%1,%2,%3}, {%4,%5,%6,%7}, {%8,%9}, {%0,%1,%2,%3};" \
        : "+f"((d)[0]), "+f"((d)[1]), "+f"((d)[2]), "+f"((d)[3]) \
        : "r"((a)[0]), "r"((a)[1]), "r"((a)[2]), "r"((a)[3]), "r"(b0), "r"(b1))
__device__ __forceinline__ void ldmx4(uint32_t* r, uint32_t addr) {
    asm volatile("ldmatrix.sync.aligned.m8n8.x4.shared.b16 {%0,%1,%2,%3}, [%4];"
        : "=r"(r[0]), "=r"(r[1]), "=r"(r[2]), "=r"(r[3]) : "r"(addr));
}
__device__ __forceinline__ void ldmx4t(uint32_t* r, uint32_t addr) {
    asm volatile("ldmatrix.sync.aligned.m8n8.x4.trans.shared.b16 {%0,%1,%2,%3}, [%4];"
        : "=r"(r[0]), "=r"(r[1]), "=r"(r[2]), "=r"(r[3]) : "r"(addr));
}
__device__ __forceinline__ void split_w(float v, __nv_bfloat16* h, __nv_bfloat16* l, long i) {
    __nv_bfloat16 hv = __float2bfloat16_rn(v);
    h[i] = hv;
    l[i] = __float2bfloat16_rn(v - __bfloat162float(hv));
}
__device__ __forceinline__ float to_tf32(float v) {
    uint32_t u;
    asm("cvt.rna.tf32.f32 %0, %1;" : "=r"(u) : "f"(v));
    return __uint_as_float(u);
}
__device__ __forceinline__ uint32_t lds_u32(uint32_t addr) {
    uint32_t v;
    asm volatile("ld.shared.b32 %0, [%1];" : "=r"(v) : "r"(addr));
    return v;
}
__device__ __forceinline__ uint32_t pack_bf2(float a, float b) {
    __nv_bfloat162 t;
    t.x = __float2bfloat16_rn(a);
    t.y = __float2bfloat16_rn(b);
    return *(uint32_t*)&t;
}

// -------------------- TF32 mma.sync batched GEMM (3-stage) ------------------
struct GP {
    const float* A; const float* B;
    float* C; float* Ct;
    int M, N, K, lda, ldb;
    long sA, sB, sC;
    int gx, gy;
};

// tile: 128x128, 8 warps (wm 0..1 x wn 0..3), warp tile 64x32
template<int AT, int BT, bool ACC, bool SPLIT>
__device__ __forceinline__ void gemm_body(const GP p, int bz)
{
    if ((int)blockIdx.x >= p.gx || (int)blockIdx.y >= p.gy) return;
    constexpr int SA = AT ? 17408 : 18432;
    constexpr int SB = BT ? 17408 : 18432;
    constexpr int STAGE = SA + SB;
    extern __shared__ char smem[];
    uint32_t sb = smem_u32(smem);
    int tid = threadIdx.x, lane = tid & 31, wid = tid >> 5;
    int wm = wid >> 2, wn = wid & 3;
    const float* a = p.A + (long)bz * p.sA;
    const float* b = p.B + (long)bz * p.sB;
    int m0 = blockIdx.y << 7, n0 = blockIdx.x << 7;
    int lda = p.lda, ldb = p.ldb;

    float acc[4][4][4];
    #pragma unroll
    for (int i = 0; i < 4; ++i)
        #pragma unroll
        for (int j = 0; j < 4; ++j)
            #pragma unroll
            for (int q = 0; q < 4; ++q) acc[i][j][q] = 0.f;

    int Lm = lane >> 3, Lr = lane & 7;
    uint32_t aoff = (uint32_t)(((Lm & 1) * 8 + Lr) * 144 + (Lm >> 1) * 16);
    uint32_t boff = (uint32_t)(((Lm >> 1) * 8 + Lr) * 144 + (Lm & 1) * 16);

    auto issue = [&](int buf, int k0) {
        uint32_t st = sb + buf * STAGE;
        #pragma unroll
        for (int j = 0; j < 4; ++j) {
            int u = tid + j * 256;
            uint32_t so; long g;
            if (AT == 0) { int r = u >> 3, s = u & 7;  so = r * 144 + s * 16;
                           g = (long)(m0 + r) * lda + k0 + s * 4; }
            else         { int r = u >> 5, s = u & 31; so = r * 544 + s * 16;
                           g = (long)(k0 + r) * lda + m0 + s * 4; }
            cpa16(st + so, a + g);
            if (BT == 0) { int r = u >> 3, s = u & 7;  so = r * 144 + s * 16;
                           g = (long)(n0 + r) * ldb + k0 + s * 4; }
            else         { int r = u >> 5, s = u & 31; so = r * 544 + s * 16;
                           g = (long)(k0 + r) * ldb + n0 + s * 4; }
            cpa16(st + SA + so, b + g);
        }
        CP_COMMIT();
    };

    const int n = p.K >> 5;
    issue(0, 0);
    if (n > 1) issue(1, 32);
    int buf = 0;
    for (int i = 0; i < n; ++i) {
        if (i + 1 < n) asm volatile("cp.async.wait_group 1;" ::: "memory");
        else           asm volatile("cp.async.wait_group 0;" ::: "memory");
        __syncthreads();
        uint32_t st = sb + buf * STAGE;
        uint32_t stB = st + SA;
        #pragma unroll
        for (int kk = 0; kk < 32; kk += 8) {
            uint32_t af[4][4];
            #pragma unroll
            for (int mt = 0; mt < 4; ++mt) {
                if (AT == 0) {
                    ldmx4(af[mt], st + (wm * 64 + mt * 16) * 144 + kk * 4 + aoff);
                } else {
                    uint32_t ra = st + (kk + (lane & 3)) * 544
                                + (wm * 64 + mt * 16 + (lane >> 2)) * 4;
                    af[mt][0] = lds_u32(ra);
                    af[mt][1] = lds_u32(ra + 32);
                    af[mt][2] = lds_u32(ra + 4 * 544);
                    af[mt][3] = lds_u32(ra + 4 * 544 + 32);
                }
            }
            uint32_t bf_[4][2];
            if (BT == 0) {
                #pragma unroll
                for (int pp = 0; pp < 2; ++pp) {
                    uint32_t r4[4];
                    ldmx4(r4, stB + (wn * 32 + pp * 16) * 144 + kk * 4 + boff);
                    bf_[pp * 2 + 0][0] = r4[0]; bf_[pp * 2 + 0][1] = r4[1];
                    bf_[pp * 2 + 1][0] = r4[2]; bf_[pp * 2 + 1][1] = r4[3];
                }
            } else {
                #pragma unroll
                for (int nt = 0; nt < 4; ++nt) {
                    uint32_t rb = stB + (kk + (lane & 3)) * 544
                                + (wn * 32 + nt * 8 + (lane >> 2)) * 4;
                    bf_[nt][0] = lds_u32(rb);
                    bf_[nt][1] = lds_u32(rb + 4 * 544);
                }
            }
            #pragma unroll
            for (int nt = 0; nt < 4; ++nt)
                #pragma unroll
                for (int mt = 0; mt < 4; ++mt)
                    MMATF(acc[mt][nt], af[mt], bf_[nt][0], bf_[nt][1]);
        }
        if (i + 2 < n) issue((i + 2) % 3, (i + 2) * 32);
        buf = (buf == 2) ? 0 : buf + 1;
    }
    float* c = p.C + (long)bz * p.sC;
    float* ct = SPLIT ? p.Ct + (long)bz * p.sC : nullptr;
    int N = p.N;
    #pragma unroll
    for (int mt = 0; mt < 4; ++mt) {
        #pragma unroll
        for (int nt = 0; nt < 4; ++nt) {
            long r0 = m0 + wm * 64 + mt * 16 + (lane >> 2);
            int  cc = n0 + wn * 32 + nt * 8 + (lane & 3) * 2;
            long o0 = r0 * (long)N + cc;
            long o1 = (r0 + 8) * (long)N + cc;
            float v00 = acc[mt][nt][0], v01 = acc[mt][nt][1];
            float v10 = acc[mt][nt][2], v11 = acc[mt][nt][3];
            if (ACC) {
                float2 t0 = *(float2*)(c + o0), t1 = *(float2*)(c + o1);
                v00 += t0.x; v01 += t0.y; v10 += t1.x; v11 += t1.y;
            }
            *(float2*)(c + o0) = make_float2(v00, v01);
            *(float2*)(c + o1) = make_float2(v10, v11);
            if (SPLIT) {
                *(float2*)(ct + o0) = make_float2(to_tf32(v00), to_tf32(v01));
                *(float2*)(ct + o1) = make_float2(to_tf32(v10), to_tf32(v11));
            }
        }
    }
}

__global__ void __launch_bounds__(256, 2) tf_nt(GP p) {
    gemm_body<0, 0, false, false>(p, blockIdx.z);
}
__global__ void __launch_bounds__(256, 2) tf_tn(GP p) {
    gemm_body<1, 1, true, true>(p, blockIdx.z);
}
__global__ void __launch_bounds__(256, 2) tf_pack_fwd(GP p1, GP p2, int z1) {
    if ((int)blockIdx.z < z1) gemm_body<0, 0, false, false>(p1, blockIdx.z);
    else                      gemm_body<0, 1, false, false>(p2, blockIdx.z - z1);
}
__global__ void __launch_bounds__(256, 2) tf_pack_qu(GP p1, GP p2, int z1) {
    if ((int)blockIdx.z < z1) gemm_body<0, 0, false, false>(p1, blockIdx.z);
    else                      gemm_body<1, 1, true, true>(p2, blockIdx.z - z1);
}
__global__ void __launch_bounds__(256, 2) tf_pack3(GP p1, GP p2, GP p3, int z1, int z2) {
    int z = blockIdx.z;
    if (z < z1)            gemm_body<0, 0, false, false>(p1, z);
    else if (z < z1 + z2)  gemm_body<0, 0, false, false>(p2, z - z1);
    else                   gemm_body<0, 1, false, false>(p3, z - z1 - z2);
}

// ------------------------ conversion kernel ---------------------------------
__global__ void cvt_tf(const float* __restrict__ x, float* __restrict__ o, long n)
{
    long i = ((long)blockIdx.x * 256 + threadIdx.x) * 4;
    if (i >= n) return;
    float4 v = *(const float4*)(x + i);
    float4 w;
    w.x = to_tf32(v.x); w.y = to_tf32(v.y); w.z = to_tf32(v.z); w.w = to_tf32(v.w);
    *(float4*)(o + i) = w;
}

// ---------------- small SGEMM for the N=12 lr GEMM --------------------------
__global__ void lr_gemm(const float* __restrict__ A, const float* __restrict__ B,
                        float* __restrict__ C)
{
    __shared__ float bs[12][128];
    int row = blockIdx.x * 2 + (threadIdx.x >> 7);
    int tid = threadIdx.x & 127;
    float acc[12];
    #pragma unroll
    for (int c = 0; c < 12; ++c) acc[c] = 0.f;
    for (int k0 = 0; k0 < 2048; k0 += 128) {
        if (threadIdx.x < 128)
            #pragma unroll
            for (int c = 0; c < 12; ++c) bs[c][tid] = B[c * 2048 + k0 + tid];
        __syncthreads();
        float a = A[(long)row * 2048 + k0 + tid];
        #pragma unroll
        for (int c = 0; c < 12; ++c) acc[c] += a * bs[c][tid];
        __syncthreads();
    }
    __shared__ float red[2][12][4];
    #pragma unroll
    for (int c = 0; c < 12; ++c) {
        float v = acc[c];
        #pragma unroll
        for (int o = 16; o > 0; o >>= 1) v += __shfl_down_sync(0xffffffffu, v, o);
        if ((tid & 31) == 0) red[threadIdx.x >> 7][c][tid >> 5] = v;
    }
    __syncthreads();
    if (tid < 12) {
        int w = threadIdx.x >> 7;
        C[(long)row * 12 + tid] = red[w][tid][0] + red[w][tid][1] + red[w][tid][2] + red[w][tid][3];
    }
}

// ------------------------- block reduce (256 thr) ---------------------------
__device__ __forceinline__ float blockReduceSum(float v, float* sred)
{
    int lane = threadIdx.x & 31;
    #pragma unroll
    for (int o = 16; o > 0; o >>= 1) v += __shfl_down_sync(0xffffffffu, v, o);
    if (lane == 0) sred[threadIdx.x >> 5] = v;
    __syncthreads();
    if (threadIdx.x < 8) {
        float r = sred[threadIdx.x];
        #pragma unroll
        for (int o = 4; o > 0; o >>= 1) r += __shfl_down_sync(0xffu, r, o);
        if (threadIdx.x == 0) sred[0] = r;
    }
    __syncthreads();
    float out = sred[0];
    __syncthreads();
    return out;
}

// --------- prep: rmsnorm+rope + silu/L2 + lr ---------------------------------
__global__ void prep_kernel(const float* __restrict__ qkv, const float* __restrict__ lrpre,
                            const float* __restrict__ qnw, const float* __restrict__ knw,
                            const float* __restrict__ qksc, const float* __restrict__ qkof,
                            const float* __restrict__ lrb, float base_lr_inv,
                            __nv_bfloat16* __restrict__ aqh, __nv_bfloat16* __restrict__ aql,
                            __nv_bfloat16* __restrict__ akh, __nv_bfloat16* __restrict__ akl,
                            __nv_bfloat16* __restrict__ avh, __nv_bfloat16* __restrict__ avl,
                            float* __restrict__ fqt, float* __restrict__ fkt,
                            float* __restrict__ fvt, float* __restrict__ lrout)
{
    __shared__ float s_q[2048];
    __shared__ float s_k[2048];
    __shared__ float sred[8];
    int row = blockIdx.x;
    int b = row >> 11, t = row & 2047;
    int tid = threadIdx.x;
    const float* qr = qkv + (long)row * 6144;
    const float* kr = qr + 2048;
    const float* vr = qr + 4096;
    const float qscale = 0.088388347648318447f * 1.4426950408889634f;

    float qv[8], kv[8], fqv[8], fkv[8], fvv[8];
    float sq = 0.f, sk = 0.f;
    float p2q[4] = {0, 0, 0, 0}, p2k[4] = {0, 0, 0, 0};
    #pragma unroll
    for (int j = 0; j < 8; ++j) {
        int i = j * 256 + tid;
        float q = qr[i], k = kr[i], v = vr[i];
        qv[j] = q; kv[j] = k;
        sq += q * q; sk += k * k;
        float fqe = (q / (1.f + expf(-q))) * qksc[i * 2 + 0] + qkof[i * 2 + 0];
        float fke = (k / (1.f + expf(-k))) * qksc[i * 2 + 1] + qkof[i * 2 + 1];
        fqv[j] = fqe; fkv[j] = fke; fvv[j] = v / (1.f + expf(-v));
        p2q[j >> 1] += fqe * fqe;
        p2k[j >> 1] += fke * fke;
        split_w(v, avh, avl, (long)row * DIMD + i);
    }
    float SQ = blockReduceSum(sq, sred);
    float SK = blockReduceSum(sk, sred);
    float G2Q[4], G2K[4];
    #pragma unroll
    for (int g = 0; g < 4; ++g) G2Q[g] = blockReduceSum(p2q[g], sred);
    #pragma unroll
    for (int g = 0; g < 4; ++g) G2K[g] = blockReduceSum(p2k[g], sred);
    float rq = rsqrtf(SQ * (1.f / 2048.f) + 1e-6f);
    float rk = rsqrtf(SK * (1.f / 2048.f) + 1e-6f);
    #pragma unroll
    for (int j = 0; j < 8; ++j) {
        int i = j * 256 + tid;
        s_q[i] = qv[j] * rq * qnw[i];
        s_k[i] = kv[j] * rk * knw[i];
        int g = j >> 1;
        long fb = (((long)(b * 4 + g)) * SEQ + t) * FDM + (i & 511);
        fqt[fb] = to_tf32(fqv[j] / (sqrtf(G2Q[g]) + 1e-12f));
        fkt[fb] = to_tf32(fkv[j] / (sqrtf(G2K[g]) + 1e-12f));
        fvt[fb] = to_tf32(fvv[j]);
    }
    __syncthreads();
    #pragma unroll
    for (int j = 0; j < 8; ++j) {
        int i = j * 256 + tid;
        int pos = i & 127;
        int fi = pos & 63;
        float invf = expf(-(float)fi * (logf(500000.f) / 64.f));
        float sn, cs;
        sincosf((float)t * invf, &sn, &cs);
        float oq, ok_;
        if (pos < 64) {
            oq  = s_q[i] * cs - s_q[i + 64] * sn;
            ok_ = s_k[i] * cs - s_k[i + 64] * sn;
        } else {
            oq  = s_q[i] * cs + s_q[i - 64] * sn;
            ok_ = s_k[i] * cs + s_k[i - 64] * sn;
        }
        split_w(oq * qscale, aqh, aql, (long)row * DIMD + i);
        split_w(ok_, akh, akl, (long)row * DIMD + i);
    }
    if (tid < 12) {
        float x = lrpre[(long)row * 12 + tid] + lrb[tid] + base_lr_inv;
        lrout[(long)row * 12 + tid] = (x > 20.f) ? x : log1pf(expf(x));
    }
}

// ------------- HMMA flash attention, register softmax (4 warps) --------------
#define ATS 272
#define O_QH 0
#define O_QL 17408
#define O_KH 34816
#define O_KL 52224
#define O_VH 69632
#define O_VL 87040
#define ATTN_SMEM 104448

__global__ void __launch_bounds__(128, 2)
attn_mma(const __nv_bfloat16* __restrict__ Qh, const __nv_bfloat16* __restrict__ Ql,
         const __nv_bfloat16* __restrict__ Kh, const __nv_bfloat16* __restrict__ Kl,
         const __nv_bfloat16* __restrict__ Vh, const __nv_bfloat16* __restrict__ Vl,
         float* __restrict__ O)
{
    extern __shared__ char smc[];
    uint32_t sb = smem_u32(smc);
    int tid = threadIdx.x, lane = tid & 31, wid = tid >> 5;
    int q0 = blockIdx.x << 6, h = blockIdx.y, b = blockIdx.z;
    int wr = wid * 16;
    uint32_t a_row = (lane & 7) + ((lane >> 3) & 1) * 8;
    uint32_t a_kb  = ((lane >> 4) & 1) * 16;
    uint32_t b_row = (lane & 7) + ((lane >> 4) & 1) * 8;
    uint32_t b_kb  = ((lane >> 3) & 1) * 16;
    uint32_t b_kr  = (lane & 7) + ((lane >> 3) & 1) * 8;
    uint32_t b_no  = ((lane >> 4) & 1) * 8;

    #pragma unroll
    for (int j = 0; j < 8; ++j) {
        int u = tid + j * 128;
        int r = u >> 4, s = u & 15;
        long g = ((long)(b * SEQ + q0 + r)) * DIMD + h * 128 + s * 8;
        cpa16(sb + O_QH + r * ATS + s * 16, Qh + g);
        cpa16(sb + O_QL + r * ATS + s * 16, Ql + g);
    }
    CP_COMMIT();

    float oacc[16][4];
    #pragma unroll
    for (int i = 0; i < 16; ++i)
        #pragma unroll
        for (int q = 0; q < 4; ++q) oacc[i][q] = 0.f;
    float m_lo = -INFINITY, m_hi = -INFINITY, l_lo = 0.f, l_hi = 0.f;

    int r_lo = q0 + wr + (lane >> 2);
    int r_hi = r_lo + 8;

    int kt_hi2 = q0 >> 6;
    int kt_lo2 = (q0 >= 1024) ? ((q0 - 1023) >> 6) : 0;
    for (int kt = kt_lo2; kt <= kt_hi2; ++kt) {
        int j0 = kt << 6;
        __syncthreads();
        #pragma unroll
        for (int j = 0; j < 8; ++j) {
            int u = tid + j * 128;
            int r = u >> 4, s = u & 15;
            long g = ((long)(b * SEQ + j0 + r)) * DIMD + h * 128 + s * 8;
            uint32_t so = r * ATS + s * 16;
            cpa16(sb + O_KH + so, Kh + g);
            cpa16(sb + O_KL + so, Kl + g);
            cpa16(sb + O_VH + so, Vh + g);
            cpa16(sb + O_VL + so, Vl + g);
        }
        CP_COMMIT();
        asm volatile("cp.async.wait_group 0;" ::: "memory");
        __syncthreads();

        float sacc[8][4];
        #pragma unroll
        for (int i = 0; i < 8; ++i)
            #pragma unroll
            for (int q = 0; q < 4; ++q) sacc[i][q] = 0.f;
        #pragma unroll
        for (int kk = 0; kk < 8; ++kk) {
            uint32_t ah4[4], al4[4];
            uint32_t ra = sb + O_QH + (wr + a_row) * ATS + kk * 32 + a_kb;
            ldmx4(ah4, ra);
            ldmx4(al4, ra + (O_QL - O_QH));
            uint32_t bh4[4][4], bl4[4][4];
            #pragma unroll
            for (int p = 0; p < 4; ++p) {
                uint32_t rb = sb + O_KH + (p * 16 + b_row) * ATS + kk * 32 + b_kb;
                ldmx4(bh4[p], rb);
                ldmx4(bl4[p], rb + (O_KL - O_KH));
            }
            #pragma unroll
            for (int nt = 0; nt < 8; ++nt) {
                uint32_t b0h = bh4[nt >> 1][(nt & 1) * 2 + 0];
                uint32_t b1h = bh4[nt >> 1][(nt & 1) * 2 + 1];
                uint32_t b0l = bl4[nt >> 1][(nt & 1) * 2 + 0];
                uint32_t b1l = bl4[nt >> 1][(nt & 1) * 2 + 1];
                MMA16816(sacc[nt], ah4, b0h, b1h);
                MMA16816(sacc[nt], ah4, b0l, b1l);
                MMA16816(sacc[nt], al4, b0h, b1h);
            }
        }
        float tmax_lo = -INFINITY, tmax_hi = -INFINITY;
        #pragma unroll
        for (int nt = 0; nt < 8; ++nt) {
            #pragma unroll
            for (int e = 0; e < 2; ++e) {
                int col = j0 + nt * 8 + (lane & 3) * 2 + e;
                bool ok0 = (col <= r_lo) && (r_lo - col < 1024);
                bool ok1 = (col <= r_hi) && (r_hi - col < 1024);
                sacc[nt][e]     = ok0 ? sacc[nt][e]     : -INFINITY;
                sacc[nt][2 + e] = ok1 ? sacc[nt][2 + e] : -INFINITY;
                tmax_lo = fmaxf(tmax_lo, sacc[nt][e]);
                tmax_hi = fmaxf(tmax_hi, sacc[nt][2 + e]);
            }
        }
        tmax_lo = fmaxf(tmax_lo, __shfl_xor_sync(0xffffffffu, tmax_lo, 1));
        tmax_lo = fmaxf(tmax_lo, __shfl_xor_sync(0xffffffffu, tmax_lo, 2));
        tmax_hi = fmaxf(tmax_hi, __shfl_xor_sync(0xffffffffu, tmax_hi, 1));
        tmax_hi = fmaxf(tmax_hi, __shfl_xor_sync(0xffffffffu, tmax_hi, 2));
        float mt_lo = fmaxf(m_lo, tmax_lo);
        float mt_hi = fmaxf(m_hi, tmax_hi);
        float mte_lo = (mt_lo > -INFINITY) ? mt_lo : 0.f;
        float mte_hi = (mt_hi > -INFINITY) ? mt_hi : 0.f;
        float corr_lo = exp2f(m_lo - mte_lo);
        float corr_hi = exp2f(m_hi - mte_hi);

        uint32_t ph[4][4], pl[4][4];
        float ls_lo = 0.f, ls_hi = 0.f;
        #pragma unroll
        for (int k2 = 0; k2 < 4; ++k2) {
            #pragma unroll
            for (int half = 0; half < 2; ++half) {
                int nt = k2 * 2 + half;
                float p00 = exp2f(sacc[nt][0] - mte_lo);
                float p01 = exp2f(sacc[nt][1] - mte_lo);
                float p10 = exp2f(sacc[nt][2] - mte_hi);
                float p11 = exp2f(sacc[nt][3] - mte_hi);
                ls_lo += p00 + p01;
                ls_hi += p10 + p11;
                uint32_t h0 = pack_bf2(p00, p01);
                uint32_t h1 = pack_bf2(p10, p11);
                __nv_bfloat162 hb0 = *(__nv_bfloat162*)&h0;
                __nv_bfloat162 hb1 = *(__nv_bfloat162*)&h1;
                uint32_t l0 = pack_bf2(p00 - __bfloat162float(hb0.x),
                                       p01 - __bfloat162float(hb0.y));
                uint32_t l1 = pack_bf2(p10 - __bfloat162float(hb1.x),
                                       p11 - __bfloat162float(hb1.y));
                ph[k2][half * 2 + 0] = h0; ph[k2][half * 2 + 1] = h1;
                pl[k2][half * 2 + 0] = l0; pl[k2][half * 2 + 1] = l1;
            }
        }
        ls_lo += __shfl_xor_sync(0xffffffffu, ls_lo, 1);
        ls_lo += __shfl_xor_sync(0xffffffffu, ls_lo, 2);
        ls_hi += __shfl_xor_sync(0xffffffffu, ls_hi, 1);
        ls_hi += __shfl_xor_sync(0xffffffffu, ls_hi, 2);
        l_lo = l_lo * corr_lo + ls_lo;
        l_hi = l_hi * corr_hi + ls_hi;
        m_lo = mt_lo; m_hi = mt_hi;

        #pragma unroll
        for (int nt = 0; nt < 16; ++nt) {
            oacc[nt][0] *= corr_lo; oacc[nt][1] *= corr_lo;
            oacc[nt][2] *= corr_hi; oacc[nt][3] *= corr_hi;
        }
        #pragma unroll
        for (int k2 = 0; k2 < 4; ++k2) {
            #pragma unroll
            for (int p2 = 0; p2 < 8; ++p2) {
                uint32_t vh4[4], vl4[4];
                uint32_t rb = sb + O_VH + (k2 * 16 + b_kr) * ATS + (p2 * 16 + b_no) * 2;
                ldmx4t(vh4, rb);
                ldmx4t(vl4, rb + (O_VL - O_VH));
                #pragma unroll
                for (int sub = 0; sub < 2; ++sub) {
                    int nt = p2 * 2 + sub;
                    uint32_t b0h = vh4[sub * 2], b1h = vh4[sub * 2 + 1];
                    uint32_t b0l = vl4[sub * 2], b1l = vl4[sub * 2 + 1];
                    MMA16816(oacc[nt], ph[k2], b0h, b1h);
                    MMA16816(oacc[nt], ph[k2], b0l, b1l);
                    MMA16816(oacc[nt], pl[k2], b0h, b1h);
                }
            }
        }
    }
    float rl0 = 1.f / l_lo, rl1 = 1.f / l_hi;
    #pragma unroll
    for (int nt = 0; nt < 16; ++nt) {
        int col = nt * 8 + (lane & 3) * 2;
        long o0 = ((long)(b * SEQ + r_lo)) * 2048 + h * 128 + col;
        long o1 = ((long)(b * SEQ + r_hi)) * 2048 + h * 128 + col;
        *(float2*)(O + o0) = make_float2(oacc[nt][0] * rl0, oacc[nt][1] * rl0);
        *(float2*)(O + o1) = make_float2(oacc[nt][2] * rl1, oacc[nt][3] * rl1);
    }
}

// --------------------------- TTT helper kernels -----------------------------
__global__ void copyw(const float* __restrict__ w0, const float* __restrict__ w1,
                      const float* __restrict__ w2,
                      float* __restrict__ o02, float* __restrict__ o02t,
                      float* __restrict__ o1, float* __restrict__ o1t)
{
    long idx = (long)blockIdx.x * 256 + threadIdx.x;
    int col = idx & 511;
    int row = (idx >> 9) & 1023;
    int h = (idx >> 19) & 3;
    long src = (long)h * 262144 + (long)(row & 511) * 512 + col;
    float v = (row < 512) ? w0[src] : w2[src];
    o02[idx] = v;
    o02t[idx] = to_tf32(v);
    if (idx < (long)2 * 1024 * 1024) {
        float v1 = w1[idx & ((long)4 * 262144 - 1)];
        o1[idx] = v1;
        o1t[idx] = to_tf32(v1);
    }
}

__global__ void elem2(const float* __restrict__ fvt, const float* __restrict__ lr,
                      const float* __restrict__ gh, const float* __restrict__ dhin,
                      float* __restrict__ dgpt, float* __restrict__ vlt,
                      float* __restrict__ htt, int ck0)
{
    long idx = (long)blockIdx.x * 256 + threadIdx.x;
    int col = idx & 511;
    long tt = idx >> 9;
    int c = tt & 1023, bh = tt >> 10;
    int b = bh >> 2, h = bh & 3;
    long row = (long)b * SEQ + ck0 + c;
    float l0 = lr[row * 12 + h], l1 = lr[row * 12 + 4 + h], l2 = lr[row * 12 + 8 + h];
    long gi = (long)bh * 1048576 + (long)c * 1024 + col;
    float g = gh[gi], hp = gh[gi + 512], d = dhin[idx];
    float sig = 1.f / (1.f + expf(-g));
    float sg = g * sig;
    htt[idx] = to_tf32(sg * hp);
    float v = fvt[((long)bh * SEQ + ck0 + c) * FDM + col];
    dgpt[gi]       = to_tf32(d * hp * (sig * (1.f + g * (1.f - sig))) * l0);
    dgpt[gi + 512] = to_tf32(d * sg * l2);
    vlt[idx]       = to_tf32(v * l1);
}

__global__ void elem3(const float* __restrict__ gh, float* __restrict__ hnt)
{
    long idx = (long)blockIdx.x * 256 + threadIdx.x;
    int col = idx & 511;
    long tt = idx >> 9;
    int c = tt & 1023, bh = tt >> 10;
    long gi = (long)bh * 1048576 + (long)c * 1024 + col;
    float g = gh[gi];
    hnt[idx] = to_tf32((g / (1.f + expf(-g))) * gh[gi + 512]);
}

// -------------------- ttt rmsnorm + add attention result --------------------
__global__ void post_kernel(const float* __restrict__ ttt, const float* __restrict__ tw,
                            const float* __restrict__ sum, float* __restrict__ smt)
{
    __shared__ float sr[4];
    int fh = blockIdx.x, row = blockIdx.y;
    int b = row >> 11, t = row & 2047;
    int bh = b * 4 + fh;
    const float* src = ttt + ((long)bh * SEQ + t) * FDM;
    int tid = threadIdx.x;
    float v[4], ss = 0.f;
    #pragma unroll
    for (int j = 0; j < 4; ++j) { v[j] = src[tid + 128 * j]; ss += v[j] * v[j]; }
    #pragma unroll
    for (int o = 16; o > 0; o >>= 1) ss += __shfl_down_sync(0xffffffffu, ss, o);
    if ((tid & 31) == 0) sr[tid >> 5] = ss;
    __syncthreads();
    float tot = sr[0] + sr[1] + sr[2] + sr[3];
    float r = rsqrtf(tot * (1.f / 512.f) + 1e-6f);
    #pragma unroll
    for (int j = 0; j < 4; ++j) {
        int i = tid + 128 * j;
        long o = (long)row * 2048 + fh * 512 + i;
        smt[o] = to_tf32(sum[o] + v[j] * r * tw[i]);
    }
}

// --------------------------------- launch -----------------------------------
#define GSYM(p, s) cudaGetSymbolAddress((void**)&(p), s)

extern "C" void kernel_launch(void* const* d_in, const int* in_sizes, int n_in,
                              void* d_out, int out_size)
{
    const float* hidden = (const float*)d_in[0];
    const float* Wqkv   = (const float*)d_in[1];
    const float* Wo     = (const float*)d_in[2];
    const float* qnw    = (const float*)d_in[3];
    const float* knw    = (const float*)d_in[4];
    const float* w0     = (const float*)d_in[5];
    const float* w1     = (const float*)d_in[6];
    const float* w2     = (const float*)d_in[7];
    const float* lrw    = (const float*)d_in[8];
    const float* lrb    = (const float*)d_in[9];
    const float* qksc   = (const float*)d_in[10];
    const float* qkof   = (const float*)d_in[11];
    const float* tttw   = (const float*)d_in[12];
    float* out = (float*)d_out;

    float *qkv, *lrpre, *lr, *pw02, *pw1, *gh, *dh, *ttt, *sum;
    GSYM(qkv, g_qkv);   GSYM(lrpre, g_lrpre); GSYM(lr, g_lr);
    GSYM(pw02, g_w02);  GSYM(pw1, g_w1);
    GSYM(gh, g_gh);     GSYM(dh, g_dh);
    GSYM(ttt, g_ttt);   GSYM(sum, g_sum);

    float *hxt,*wqt,*wot,*fqt,*fkt,*fvt,*w02t,*w1t,*dgpt,*vlt,*htt,*hnt,*smt;
    GSYM(hxt, g_hx_t); GSYM(wqt, g_wq_t); GSYM(wot, g_wo_t);
    GSYM(fqt, g_fq_t); GSYM(fkt, g_fk_t); GSYM(fvt, g_fv_t);
    GSYM(w02t, g_w02_t); GSYM(w1t, g_w1_t);
    GSYM(dgpt, g_dgp_t); GSYM(vlt, g_vl_t); GSYM(htt, g_ht_t);
    GSYM(hnt, g_hn_t); GSYM(smt, g_sm_t);

    __nv_bfloat16 *aqh,*aql,*akh,*akl,*avh,*avl;
    GSYM(aqh, g_aq_h); GSYM(aql, g_aq_l); GSYM(akh, g_ak_h); GSYM(akl, g_ak_l);
    GSYM(avh, g_av_h); GSYM(avl, g_av_l);

    cudaFuncSetAttribute(tf_nt, cudaFuncAttributeMaxDynamicSharedMemorySize, 110592);
    cudaFuncSetAttribute(tf_tn, cudaFuncAttributeMaxDynamicSharedMemorySize, 104448);
    cudaFuncSetAttribute(tf_pack_fwd, cudaFuncAttributeMaxDynamicSharedMemorySize, 110592);
    cudaFuncSetAttribute(tf_pack_qu, cudaFuncAttributeMaxDynamicSharedMemorySize, 110592);
    cudaFuncSetAttribute(tf_pack3, cudaFuncAttributeMaxDynamicSharedMemorySize, 110592);
    cudaFuncSetAttribute(attn_mma, cudaFuncAttributeMaxDynamicSharedMemorySize, ATTN_SMEM);

    cvt_tf<<<8192, 256>>>(hidden, hxt, (long)4096 * 2048);
    cvt_tf<<<12288, 256>>>(Wqkv, wqt, (long)6144 * 2048);
    cvt_tf<<<4096, 256>>>(Wo, wot, (long)2048 * 2048);

    {
        GP p{hxt, wqt, qkv, nullptr, 4096, 6144, 2048, 2048, 2048, 0, 0, 0, 48, 32};
        tf_nt<<<dim3(48, 32, 1), 256, 110592>>>(p);
    }
    lr_gemm<<<2048, 256>>>(hidden, lrw, lrpre);

    float base = (float)(0.001 + log(-expm1(-0.001)));
    prep_kernel<<<4096, 256>>>(qkv, lrpre, qnw, knw, qksc, qkof, lrb, base,
                               aqh, aql, akh, akl, avh, avl,
                               fqt, fkt, fvt, lr);
    attn_mma<<<dim3(32, 16, 2), 128, ATTN_SMEM>>>(aqh, aql, akh, akl, avh, avl, sum);

    copyw<<<16384, 256>>>(w0, w1, w2, pw02, w02t, pw1, w1t);

    long sSeq = (long)SEQ * FDM;
    long sChk = (long)1024 * FDM;
    long sW   = (long)FDM * FDM;
    long sW02 = (long)1024 * FDM;
    long sGH  = (long)1024 * 1024;

    // ---- chunk 0 ----
    {
        GP p1{fkt, w02t, gh, nullptr, 1024, 1024, 512, 512, 512, sSeq, sW02, sGH, 8, 8};
        GP p2{fvt, w1t, dh, nullptr, 1024, 512, 512, 512, 512, sSeq, sW, sChk, 4, 8};
        tf_pack_fwd<<<dim3(8, 8, 16), 256, 110592>>>(p1, p2, 8);
    }
    elem2<<<16384, 256>>>(fvt, lr, gh, dh, dgpt, vlt, htt, 0);
    {
        // W02 update only (W1 update moved into the qpass launch)
        GP p{dgpt, fkt, pw02, w02t, 1024, 512, 1024, 1024, 512, sGH, sSeq, sW02, 4, 8};
        tf_tn<<<dim3(4, 8, 8), 256, 104448>>>(p);
    }
    {
        // qpass (needs updated W02) || W1 update (independent of qpass)
        GP p1{fqt, w02t, gh, nullptr, 1024, 1024, 512, 512, 512, sSeq, sW02, sGH, 8, 8};
        GP p2{vlt, htt, pw1, w1t, 512, 512, 1024, 512, 512, sChk, sChk, sW, 4, 4};
        tf_pack_qu<<<dim3(8, 8, 16), 256, 110592>>>(p1, p2, 8);
    }
    elem3<<<16384, 256>>>(gh, hnt);

    long co1 = (long)1024 * FDM;
    // ---- final(ck0) || fwd(ck1) packed ----
    {
        GP p1{hnt, w1t, ttt, nullptr, 1024, 512, 512, 512, 512, sChk, sW, sSeq, 4, 8};
        GP p2{fkt + co1, w02t, gh, nullptr, 1024, 1024, 512, 512, 512, sSeq, sW02, sGH, 8, 8};
        GP p3{fvt + co1, w1t, dh, nullptr, 1024, 512, 512, 512, 512, sSeq, sW, sChk, 4, 8};
        tf_pack3<<<dim3(8, 8, 24), 256, 110592>>>(p1, p2, p3, 8, 8);
    }
    // ---- chunk 1 ----
    elem2<<<16384, 256>>>(fvt, lr, gh, dh, dgpt, vlt, htt, 1024);
    {
        GP p{dgpt, fkt + co1, pw02, w02t, 1024, 512, 1024, 1024, 512, sGH, sSeq, sW02, 4, 8};
        tf_tn<<<dim3(4, 8, 8), 256, 104448>>>(p);
    }
    {
        GP p1{fqt + co1, w02t, gh, nullptr, 1024, 1024, 512, 512, 512, sSeq, sW02, sGH, 8, 8};
        GP p2{vlt, htt, pw1, w1t, 512, 512, 1024, 512, 512, sChk, sChk, sW, 4, 4};
        tf_pack_qu<<<dim3(8, 8, 16), 256, 110592>>>(p1, p2, 8);
    }
    elem3<<<16384, 256>>>(gh, hnt);
    {
        GP p{hnt, w1t, ttt + co1, nullptr, 1024, 512, 512, 512, 512, sChk, sW, sSeq, 4, 8};
        tf_nt<<<dim3(4, 8, 8), 256, 110592>>>(p);
    }

    post_kernel<<<dim3(4, 4096), 128>>>(ttt, tttw, sum, smt);
    {
        GP p{smt, wot, out, nullptr, 4096, 2048, 2048, 2048, 2048, 0, 0, 0, 16, 32};
        tf_nt<<<dim3(16, 32, 1), 256, 110592>>>(p);
    }
}

// round 17
// speedup vs baseline: 1.0912x; 1.0356x over previous
#include <cuda_runtime.h>
#include <cuda_bf16.h>
#include <cstdint>
#include <math.h>

#define SEQ 2048
#define DIMD 2048
#define FDM 512

// ------------------------- fp32 scratch (device globals) --------------------
__device__ float g_qkv [(size_t)4096 * 6144];
__device__ float g_lrpre[(size_t)4096 * 12];
__device__ float g_lr  [(size_t)4096 * 12];
__device__ float g_w02 [(size_t)8 * 1024 * FDM];
__device__ float g_w1  [(size_t)8 * FDM * FDM];
__device__ float g_gh  [(size_t)8 * 1024 * 1024];
__device__ float g_dh  [(size_t)8 * 1024 * FDM];
__device__ float g_ttt [(size_t)8 * SEQ * FDM];
__device__ float g_sum [(size_t)4096 * 2048];

// ---------------------- tf32 (pre-rounded fp32) operands --------------------
__device__ float g_hx_t [(size_t)4096 * 2048];
__device__ float g_wq_t [(size_t)6144 * 2048];
__device__ float g_wo_t [(size_t)2048 * 2048];
__device__ float g_fq_t [(size_t)8 * SEQ * FDM];
__device__ float g_fk_t [(size_t)8 * SEQ * FDM];
__device__ float g_fv_t [(size_t)8 * SEQ * FDM];
__device__ float g_w02_t[(size_t)8 * 1024 * FDM];
__device__ float g_w1_t [(size_t)8 * FDM * FDM];
__device__ float g_dgp_t[(size_t)8 * 1024 * 1024];
__device__ float g_vl_t [(size_t)8 * 1024 * FDM];
__device__ float g_ht_t [(size_t)8 * 1024 * FDM];
__device__ float g_hn_t [(size_t)8 * 1024 * FDM];
__device__ float g_sm_t [(size_t)4096 * 2048];

// ------------------- bf16 hi/lo (attention only) ----------------------------
__device__ __nv_bfloat16 g_aq_h[(size_t)4096*2048], g_aq_l[(size_t)4096*2048];
__device__ __nv_bfloat16 g_ak_h[(size_t)4096*2048], g_ak_l[(size_t)4096*2048];
__device__ __nv_bfloat16 g_av_h[(size_t)4096*2048], g_av_l[(size_t)4096*2048];

// ------------------------------ helpers -------------------------------------
__device__ __forceinline__ uint32_t smem_u32(const void* p) {
    uint32_t a;
    asm("{ .reg .u64 t; cvta.to.shared.u64 t, %1; cvt.u32.u64 %0, t; }" : "=r"(a) : "l"(p));
    return a;
}
__device__ __forceinline__ void cpa16(uint32_t s, const void* g) {
    asm volatile("cp.async.cg.shared.global [%0], [%1], 16;" :: "r"(s), "l"(g));
}
#define CP_COMMIT() asm volatile("cp.async.commit_group;" ::: "memory")
#define MMA16816(d, a, b0, b1) \
    asm volatile("mma.sync.aligned.m16n8k16.row.col.f32.bf16.bf16.f32 " \
        "{%0,%1,%2,%3}, {%4,%5,%6,%7}, {%8,%9}, {%0,%1,%2,%3};" \
        : "+f"((d)[0]), "+f"((d)[1]), "+f"((d)[2]), "+f"((d)[3]) \
        : "r"((a)[0]), "r"((a)[1]), "r"((a)[2]), "r"((a)[3]), "r"(b0), "r"(b1))
#define MMATF(d, a, b0, b1) \
    asm volatile("mma.sync.aligned.m16n8k8.row.col.f32.tf32.tf32.f32 " \
        "{%0,%1,%2,%3}, {%4,%5,%6,%7}, {%8,%9}, {%0,%1,%2,%3};" \
        : "+f"((d)[0]), "+f"((d)[1]), "+f"((d)[2]), "+f"((d)[3]) \
        : "r"((a)[0]), "r"((a)[1]), "r"((a)[2]), "r"((a)[3]), "r"(b0), "r"(b1))
__device__ __forceinline__ void ldmx4(uint32_t* r, uint32_t addr) {
    asm volatile("ldmatrix.sync.aligned.m8n8.x4.shared.b16 {%0,%1,%2,%3}, [%4];"
        : "=r"(r[0]), "=r"(r[1]), "=r"(r[2]), "=r"(r[3]) : "r"(addr));
}
__device__ __forceinline__ void ldmx4t(uint32_t* r, uint32_t addr) {
    asm volatile("ldmatrix.sync.aligned.m8n8.x4.trans.shared.b16 {%0,%1,%2,%3}, [%4];"
        : "=r"(r[0]), "=r"(r[1]), "=r"(r[2]), "=r"(r[3]) : "r"(addr));
}
__device__ __forceinline__ void split_w(float v, __nv_bfloat16* h, __nv_bfloat16* l, long i) {
    __nv_bfloat16 hv = __float2bfloat16_rn(v);
    h[i] = hv;
    l[i] = __float2bfloat16_rn(v - __bfloat162float(hv));
}
__device__ __forceinline__ float to_tf32(float v) {
    uint32_t u;
    asm("cvt.rna.tf32.f32 %0, %1;" : "=r"(u) : "f"(v));
    return __uint_as_float(u);
}
__device__ __forceinline__ uint32_t lds_u32(uint32_t addr) {
    uint32_t v;
    asm volatile("ld.shared.b32 %0, [%1];" : "=r"(v) : "r"(addr));
    return v;
}
__device__ __forceinline__ uint32_t pack_bf2(float a, float b) {
    __nv_bfloat162 t;
    t.x = __float2bfloat16_rn(a);
    t.y = __float2bfloat16_rn(b);
    return *(uint32_t*)&t;
}

// -------------------- TF32 mma.sync batched GEMM (3-stage) ------------------
struct GP {
    const float* A; const float* B;
    float* C; float* Ct;
    int M, N, K, lda, ldb;
    long sA, sB, sC;
    int gx, gy;
};

// tile: 128x128, 8 warps (wm 0..1 x wn 0..3), warp tile 64x32
// SWI: W02 rows interleaved (2i=W0, 2i+1=W2); epilogue computes
//      silu(gate)*hpre in registers and writes Ct[M, N/2] (tf32-rounded).
template<int AT, int BT, bool ACC, bool SPLIT, bool SWI>
__device__ __forceinline__ void gemm_body(const GP p, int bz)
{
    if ((int)blockIdx.x >= p.gx || (int)blockIdx.y >= p.gy) return;
    constexpr int SA = AT ? 17408 : 18432;
    constexpr int SB = BT ? 17408 : 18432;
    constexpr int STAGE = SA + SB;
    extern __shared__ char smem[];
    uint32_t sb = smem_u32(smem);
    int tid = threadIdx.x, lane = tid & 31, wid = tid >> 5;
    int wm = wid >> 2, wn = wid & 3;
    const float* a = p.A + (long)bz * p.sA;
    const float* b = p.B + (long)bz * p.sB;
    int m0 = blockIdx.y << 7, n0 = blockIdx.x << 7;
    int lda = p.lda, ldb = p.ldb;

    float acc[4][4][4];
    #pragma unroll
    for (int i = 0; i < 4; ++i)
        #pragma unroll
        for (int j = 0; j < 4; ++j)
            #pragma unroll
            for (int q = 0; q < 4; ++q) acc[i][j][q] = 0.f;

    int Lm = lane >> 3, Lr = lane & 7;
    uint32_t aoff = (uint32_t)(((Lm & 1) * 8 + Lr) * 144 + (Lm >> 1) * 16);
    uint32_t boff = (uint32_t)(((Lm >> 1) * 8 + Lr) * 144 + (Lm & 1) * 16);

    auto issue = [&](int buf, int k0) {
        uint32_t st = sb + buf * STAGE;
        #pragma unroll
        for (int j = 0; j < 4; ++j) {
            int u = tid + j * 256;
            uint32_t so; long g;
            if (AT == 0) { int r = u >> 3, s = u & 7;  so = r * 144 + s * 16;
                           g = (long)(m0 + r) * lda + k0 + s * 4; }
            else         { int r = u >> 5, s = u & 31; so = r * 544 + s * 16;
                           g = (long)(k0 + r) * lda + m0 + s * 4; }
            cpa16(st + so, a + g);
            if (BT == 0) { int r = u >> 3, s = u & 7;  so = r * 144 + s * 16;
                           g = (long)(n0 + r) * ldb + k0 + s * 4; }
            else         { int r = u >> 5, s = u & 31; so = r * 544 + s * 16;
                           g = (long)(k0 + r) * ldb + n0 + s * 4; }
            cpa16(st + SA + so, b + g);
        }
        CP_COMMIT();
    };

    const int n = p.K >> 5;
    issue(0, 0);
    if (n > 1) issue(1, 32);
    int buf = 0;
    for (int i = 0; i < n; ++i) {
        if (i + 1 < n) asm volatile("cp.async.wait_group 1;" ::: "memory");
        else           asm volatile("cp.async.wait_group 0;" ::: "memory");
        __syncthreads();
        uint32_t st = sb + buf * STAGE;
        uint32_t stB = st + SA;
        #pragma unroll
        for (int kk = 0; kk < 32; kk += 8) {
            uint32_t af[4][4];
            #pragma unroll
            for (int mt = 0; mt < 4; ++mt) {
                if (AT == 0) {
                    ldmx4(af[mt], st + (wm * 64 + mt * 16) * 144 + kk * 4 + aoff);
                } else {
                    uint32_t ra = st + (kk + (lane & 3)) * 544
                                + (wm * 64 + mt * 16 + (lane >> 2)) * 4;
                    af[mt][0] = lds_u32(ra);
                    af[mt][1] = lds_u32(ra + 32);
                    af[mt][2] = lds_u32(ra + 4 * 544);
                    af[mt][3] = lds_u32(ra + 4 * 544 + 32);
                }
            }
            uint32_t bf_[4][2];
            if (BT == 0) {
                #pragma unroll
                for (int pp = 0; pp < 2; ++pp) {
                    uint32_t r4[4];
                    ldmx4(r4, stB + (wn * 32 + pp * 16) * 144 + kk * 4 + boff);
                    bf_[pp * 2 + 0][0] = r4[0]; bf_[pp * 2 + 0][1] = r4[1];
                    bf_[pp * 2 + 1][0] = r4[2]; bf_[pp * 2 + 1][1] = r4[3];
                }
            } else {
                #pragma unroll
                for (int nt = 0; nt < 4; ++nt) {
                    uint32_t rb = stB + (kk + (lane & 3)) * 544
                                + (wn * 32 + nt * 8 + (lane >> 2)) * 4;
                    bf_[nt][0] = lds_u32(rb);
                    bf_[nt][1] = lds_u32(rb + 4 * 544);
                }
            }
            #pragma unroll
            for (int nt = 0; nt < 4; ++nt)
                #pragma unroll
                for (int mt = 0; mt < 4; ++mt)
                    MMATF(acc[mt][nt], af[mt], bf_[nt][0], bf_[nt][1]);
        }
        if (i + 2 < n) issue((i + 2) % 3, (i + 2) * 32);
        buf = (buf == 2) ? 0 : buf + 1;
    }
    int N = p.N;
    if (SWI) {
        float* hn = p.Ct + (long)bz * p.sC;
        int Nh = N >> 1;
        #pragma unroll
        for (int mt = 0; mt < 4; ++mt) {
            #pragma unroll
            for (int nt = 0; nt < 4; ++nt) {
                long r0 = m0 + wm * 64 + mt * 16 + (lane >> 2);
                int  cc = n0 + wn * 32 + nt * 8 + (lane & 3) * 2;   // even
                float g0 = acc[mt][nt][0], h0 = acc[mt][nt][1];
                float g1 = acc[mt][nt][2], h1 = acc[mt][nt][3];
                float s0 = (g0 / (1.f + expf(-g0))) * h0;
                float s1 = (g1 / (1.f + expf(-g1))) * h1;
                hn[r0 * (long)Nh + (cc >> 1)]       = to_tf32(s0);
                hn[(r0 + 8) * (long)Nh + (cc >> 1)] = to_tf32(s1);
            }
        }
        return;
    }
    float* c = p.C + (long)bz * p.sC;
    float* ct = SPLIT ? p.Ct + (long)bz * p.sC : nullptr;
    #pragma unroll
    for (int mt = 0; mt < 4; ++mt) {
        #pragma unroll
        for (int nt = 0; nt < 4; ++nt) {
            long r0 = m0 + wm * 64 + mt * 16 + (lane >> 2);
            int  cc = n0 + wn * 32 + nt * 8 + (lane & 3) * 2;
            long o0 = r0 * (long)N + cc;
            long o1 = (r0 + 8) * (long)N + cc;
            float v00 = acc[mt][nt][0], v01 = acc[mt][nt][1];
            float v10 = acc[mt][nt][2], v11 = acc[mt][nt][3];
            if (ACC) {
                float2 t0 = *(float2*)(c + o0), t1 = *(float2*)(c + o1);
                v00 += t0.x; v01 += t0.y; v10 += t1.x; v11 += t1.y;
            }
            *(float2*)(c + o0) = make_float2(v00, v01);
            *(float2*)(c + o1) = make_float2(v10, v11);
            if (SPLIT) {
                *(float2*)(ct + o0) = make_float2(to_tf32(v00), to_tf32(v01));
                *(float2*)(ct + o1) = make_float2(to_tf32(v10), to_tf32(v11));
            }
        }
    }
}

__global__ void __launch_bounds__(256, 2) tf_nt(GP p) {
    gemm_body<0, 0, false, false, false>(p, blockIdx.z);
}
__global__ void __launch_bounds__(256, 2) tf_swi(GP p) {
    gemm_body<0, 0, false, false, true>(p, blockIdx.z);
}
__global__ void __launch_bounds__(256, 2) tf_pack_fwd(GP p1, GP p2, int z1) {
    if ((int)blockIdx.z < z1) gemm_body<0, 0, false, false, false>(p1, blockIdx.z);
    else                      gemm_body<0, 1, false, false, false>(p2, blockIdx.z - z1);
}
__global__ void __launch_bounds__(256, 2) tf_pack_upd(GP p1, GP p2, int z1) {
    if ((int)blockIdx.z < z1) gemm_body<1, 1, true, true, false>(p1, blockIdx.z);
    else                      gemm_body<1, 1, true, true, false>(p2, blockIdx.z - z1);
}
__global__ void __launch_bounds__(256, 2) tf_pack3(GP p1, GP p2, GP p3, int z1, int z2) {
    int z = blockIdx.z;
    if (z < z1)            gemm_body<0, 0, false, false, false>(p1, z);
    else if (z < z1 + z2)  gemm_body<0, 0, false, false, false>(p2, z - z1);
    else                   gemm_body<0, 1, false, false, false>(p3, z - z1 - z2);
}

// ------------------------ conversion kernel ---------------------------------
__global__ void cvt_tf(const float* __restrict__ x, float* __restrict__ o, long n)
{
    long i = ((long)blockIdx.x * 256 + threadIdx.x) * 4;
    if (i >= n) return;
    float4 v = *(const float4*)(x + i);
    float4 w;
    w.x = to_tf32(v.x); w.y = to_tf32(v.y); w.z = to_tf32(v.z); w.w = to_tf32(v.w);
    *(float4*)(o + i) = w;
}

// ---------------- small SGEMM for the N=12 lr GEMM --------------------------
__global__ void lr_gemm(const float* __restrict__ A, const float* __restrict__ B,
                        float* __restrict__ C)
{
    __shared__ float bs[12][128];
    int row = blockIdx.x * 2 + (threadIdx.x >> 7);
    int tid = threadIdx.x & 127;
    float acc[12];
    #pragma unroll
    for (int c = 0; c < 12; ++c) acc[c] = 0.f;
    for (int k0 = 0; k0 < 2048; k0 += 128) {
        if (threadIdx.x < 128)
            #pragma unroll
            for (int c = 0; c < 12; ++c) bs[c][tid] = B[c * 2048 + k0 + tid];
        __syncthreads();
        float a = A[(long)row * 2048 + k0 + tid];
        #pragma unroll
        for (int c = 0; c < 12; ++c) acc[c] += a * bs[c][tid];
        __syncthreads();
    }
    __shared__ float red[2][12][4];
    #pragma unroll
    for (int c = 0; c < 12; ++c) {
        float v = acc[c];
        #pragma unroll
        for (int o = 16; o > 0; o >>= 1) v += __shfl_down_sync(0xffffffffu, v, o);
        if ((tid & 31) == 0) red[threadIdx.x >> 7][c][tid >> 5] = v;
    }
    __syncthreads();
    if (tid < 12) {
        int w = threadIdx.x >> 7;
        C[(long)row * 12 + tid] = red[w][tid][0] + red[w][tid][1] + red[w][tid][2] + red[w][tid][3];
    }
}

// ------------------------- block reduce (256 thr) ---------------------------
__device__ __forceinline__ float blockReduceSum(float v, float* sred)
{
    int lane = threadIdx.x & 31;
    #pragma unroll
    for (int o = 16; o > 0; o >>= 1) v += __shfl_down_sync(0xffffffffu, v, o);
    if (lane == 0) sred[threadIdx.x >> 5] = v;
    __syncthreads();
    if (threadIdx.x < 8) {
        float r = sred[threadIdx.x];
        #pragma unroll
        for (int o = 4; o > 0; o >>= 1) r += __shfl_down_sync(0xffu, r, o);
        if (threadIdx.x == 0) sred[0] = r;
    }
    __syncthreads();
    float out = sred[0];
    __syncthreads();
    return out;
}

// --------- prep: rmsnorm+rope + silu/L2 + lr ---------------------------------
__global__ void prep_kernel(const float* __restrict__ qkv, const float* __restrict__ lrpre,
                            const float* __restrict__ qnw, const float* __restrict__ knw,
                            const float* __restrict__ qksc, const float* __restrict__ qkof,
                            const float* __restrict__ lrb, float base_lr_inv,
                            __nv_bfloat16* __restrict__ aqh, __nv_bfloat16* __restrict__ aql,
                            __nv_bfloat16* __restrict__ akh, __nv_bfloat16* __restrict__ akl,
                            __nv_bfloat16* __restrict__ avh, __nv_bfloat16* __restrict__ avl,
                            float* __restrict__ fqt, float* __restrict__ fkt,
                            float* __restrict__ fvt, float* __restrict__ lrout)
{
    __shared__ float s_q[2048];
    __shared__ float s_k[2048];
    __shared__ float sred[8];
    int row = blockIdx.x;
    int b = row >> 11, t = row & 2047;
    int tid = threadIdx.x;
    const float* qr = qkv + (long)row * 6144;
    const float* kr = qr + 2048;
    const float* vr = qr + 4096;
    const float qscale = 0.088388347648318447f * 1.4426950408889634f;

    float qv[8], kv[8], fqv[8], fkv[8], fvv[8];
    float sq = 0.f, sk = 0.f;
    float p2q[4] = {0, 0, 0, 0}, p2k[4] = {0, 0, 0, 0};
    #pragma unroll
    for (int j = 0; j < 8; ++j) {
        int i = j * 256 + tid;
        float q = qr[i], k = kr[i], v = vr[i];
        qv[j] = q; kv[j] = k;
        sq += q * q; sk += k * k;
        float fqe = (q / (1.f + expf(-q))) * qksc[i * 2 + 0] + qkof[i * 2 + 0];
        float fke = (k / (1.f + expf(-k))) * qksc[i * 2 + 1] + qkof[i * 2 + 1];
        fqv[j] = fqe; fkv[j] = fke; fvv[j] = v / (1.f + expf(-v));
        p2q[j >> 1] += fqe * fqe;
        p2k[j >> 1] += fke * fke;
        split_w(v, avh, avl, (long)row * DIMD + i);
    }
    float SQ = blockReduceSum(sq, sred);
    float SK = blockReduceSum(sk, sred);
    float G2Q[4], G2K[4];
    #pragma unroll
    for (int g = 0; g < 4; ++g) G2Q[g] = blockReduceSum(p2q[g], sred);
    #pragma unroll
    for (int g = 0; g < 4; ++g) G2K[g] = blockReduceSum(p2k[g], sred);
    float rq = rsqrtf(SQ * (1.f / 2048.f) + 1e-6f);
    float rk = rsqrtf(SK * (1.f / 2048.f) + 1e-6f);
    #pragma unroll
    for (int j = 0; j < 8; ++j) {
        int i = j * 256 + tid;
        s_q[i] = qv[j] * rq * qnw[i];
        s_k[i] = kv[j] * rk * knw[i];
        int g = j >> 1;
        long fb = (((long)(b * 4 + g)) * SEQ + t) * FDM + (i & 511);
        fqt[fb] = to_tf32(fqv[j] / (sqrtf(G2Q[g]) + 1e-12f));
        fkt[fb] = to_tf32(fkv[j] / (sqrtf(G2K[g]) + 1e-12f));
        fvt[fb] = to_tf32(fvv[j]);
    }
    __syncthreads();
    #pragma unroll
    for (int j = 0; j < 8; ++j) {
        int i = j * 256 + tid;
        int pos = i & 127;
        int fi = pos & 63;
        float invf = expf(-(float)fi * (logf(500000.f) / 64.f));
        float sn, cs;
        sincosf((float)t * invf, &sn, &cs);
        float oq, ok_;
        if (pos < 64) {
            oq  = s_q[i] * cs - s_q[i + 64] * sn;
            ok_ = s_k[i] * cs - s_k[i + 64] * sn;
        } else {
            oq  = s_q[i] * cs + s_q[i - 64] * sn;
            ok_ = s_k[i] * cs + s_k[i - 64] * sn;
        }
        split_w(oq * qscale, aqh, aql, (long)row * DIMD + i);
        split_w(ok_, akh, akl, (long)row * DIMD + i);
    }
    if (tid < 12) {
        float x = lrpre[(long)row * 12 + tid] + lrb[tid] + base_lr_inv;
        lrout[(long)row * 12 + tid] = (x > 20.f) ? x : log1pf(expf(x));
    }
}

// ------------- HMMA flash attention, register softmax (4 warps) --------------
#define ATS 272
#define O_QH 0
#define O_QL 17408
#define O_KH 34816
#define O_KL 52224
#define O_VH 69632
#define O_VL 87040
#define ATTN_SMEM 104448

__global__ void __launch_bounds__(128, 2)
attn_mma(const __nv_bfloat16* __restrict__ Qh, const __nv_bfloat16* __restrict__ Ql,
         const __nv_bfloat16* __restrict__ Kh, const __nv_bfloat16* __restrict__ Kl,
         const __nv_bfloat16* __restrict__ Vh, const __nv_bfloat16* __restrict__ Vl,
         float* __restrict__ O)
{
    extern __shared__ char smc[];
    uint32_t sb = smem_u32(smc);
    int tid = threadIdx.x, lane = tid & 31, wid = tid >> 5;
    int q0 = blockIdx.x << 6, h = blockIdx.y, b = blockIdx.z;
    int wr = wid * 16;
    uint32_t a_row = (lane & 7) + ((lane >> 3) & 1) * 8;
    uint32_t a_kb  = ((lane >> 4) & 1) * 16;
    uint32_t b_row = (lane & 7) + ((lane >> 4) & 1) * 8;
    uint32_t b_kb  = ((lane >> 3) & 1) * 16;
    uint32_t b_kr  = (lane & 7) + ((lane >> 3) & 1) * 8;
    uint32_t b_no  = ((lane >> 4) & 1) * 8;

    #pragma unroll
    for (int j = 0; j < 8; ++j) {
        int u = tid + j * 128;
        int r = u >> 4, s = u & 15;
        long g = ((long)(b * SEQ + q0 + r)) * DIMD + h * 128 + s * 8;
        cpa16(sb + O_QH + r * ATS + s * 16, Qh + g);
        cpa16(sb + O_QL + r * ATS + s * 16, Ql + g);
    }
    CP_COMMIT();

    float oacc[16][4];
    #pragma unroll
    for (int i = 0; i < 16; ++i)
        #pragma unroll
        for (int q = 0; q < 4; ++q) oacc[i][q] = 0.f;
    float m_lo = -INFINITY, m_hi = -INFINITY, l_lo = 0.f, l_hi = 0.f;

    int r_lo = q0 + wr + (lane >> 2);
    int r_hi = r_lo + 8;

    int kt_hi2 = q0 >> 6;
    int kt_lo2 = (q0 >= 1024) ? ((q0 - 1023) >> 6) : 0;
    for (int kt = kt_lo2; kt <= kt_hi2; ++kt) {
        int j0 = kt << 6;
        __syncthreads();
        #pragma unroll
        for (int j = 0; j < 8; ++j) {
            int u = tid + j * 128;
            int r = u >> 4, s = u & 15;
            long g = ((long)(b * SEQ + j0 + r)) * DIMD + h * 128 + s * 8;
            uint32_t so = r * ATS + s * 16;
            cpa16(sb + O_KH + so, Kh + g);
            cpa16(sb + O_KL + so, Kl + g);
            cpa16(sb + O_VH + so, Vh + g);
            cpa16(sb + O_VL + so, Vl + g);
        }
        CP_COMMIT();
        asm volatile("cp.async.wait_group 0;" ::: "memory");
        __syncthreads();

        float sacc[8][4];
        #pragma unroll
        for (int i = 0; i < 8; ++i)
            #pragma unroll
            for (int q = 0; q < 4; ++q) sacc[i][q] = 0.f;
        #pragma unroll
        for (int kk = 0; kk < 8; ++kk) {
            uint32_t ah4[4], al4[4];
            uint32_t ra = sb + O_QH + (wr + a_row) * ATS + kk * 32 + a_kb;
            ldmx4(ah4, ra);
            ldmx4(al4, ra + (O_QL - O_QH));
            uint32_t bh4[4][4], bl4[4][4];
            #pragma unroll
            for (int p = 0; p < 4; ++p) {
                uint32_t rb = sb + O_KH + (p * 16 + b_row) * ATS + kk * 32 + b_kb;
                ldmx4(bh4[p], rb);
                ldmx4(bl4[p], rb + (O_KL - O_KH));
            }
            #pragma unroll
            for (int nt = 0; nt < 8; ++nt) {
                uint32_t b0h = bh4[nt >> 1][(nt & 1) * 2 + 0];
                uint32_t b1h = bh4[nt >> 1][(nt & 1) * 2 + 1];
                uint32_t b0l = bl4[nt >> 1][(nt & 1) * 2 + 0];
                uint32_t b1l = bl4[nt >> 1][(nt & 1) * 2 + 1];
                MMA16816(sacc[nt], ah4, b0h, b1h);
                MMA16816(sacc[nt], ah4, b0l, b1l);
                MMA16816(sacc[nt], al4, b0h, b1h);
            }
        }
        float tmax_lo = -INFINITY, tmax_hi = -INFINITY;
        #pragma unroll
        for (int nt = 0; nt < 8; ++nt) {
            #pragma unroll
            for (int e = 0; e < 2; ++e) {
                int col = j0 + nt * 8 + (lane & 3) * 2 + e;
                bool ok0 = (col <= r_lo) && (r_lo - col < 1024);
                bool ok1 = (col <= r_hi) && (r_hi - col < 1024);
                sacc[nt][e]     = ok0 ? sacc[nt][e]     : -INFINITY;
                sacc[nt][2 + e] = ok1 ? sacc[nt][2 + e] : -INFINITY;
                tmax_lo = fmaxf(tmax_lo, sacc[nt][e]);
                tmax_hi = fmaxf(tmax_hi, sacc[nt][2 + e]);
            }
        }
        tmax_lo = fmaxf(tmax_lo, __shfl_xor_sync(0xffffffffu, tmax_lo, 1));
        tmax_lo = fmaxf(tmax_lo, __shfl_xor_sync(0xffffffffu, tmax_lo, 2));
        tmax_hi = fmaxf(tmax_hi, __shfl_xor_sync(0xffffffffu, tmax_hi, 1));
        tmax_hi = fmaxf(tmax_hi, __shfl_xor_sync(0xffffffffu, tmax_hi, 2));
        float mt_lo = fmaxf(m_lo, tmax_lo);
        float mt_hi = fmaxf(m_hi, tmax_hi);
        float mte_lo = (mt_lo > -INFINITY) ? mt_lo : 0.f;
        float mte_hi = (mt_hi > -INFINITY) ? mt_hi : 0.f;
        float corr_lo = exp2f(m_lo - mte_lo);
        float corr_hi = exp2f(m_hi - mte_hi);

        uint32_t ph[4][4], pl[4][4];
        float ls_lo = 0.f, ls_hi = 0.f;
        #pragma unroll
        for (int k2 = 0; k2 < 4; ++k2) {
            #pragma unroll
            for (int half = 0; half < 2; ++half) {
                int nt = k2 * 2 + half;
                float p00 = exp2f(sacc[nt][0] - mte_lo);
                float p01 = exp2f(sacc[nt][1] - mte_lo);
                float p10 = exp2f(sacc[nt][2] - mte_hi);
                float p11 = exp2f(sacc[nt][3] - mte_hi);
                ls_lo += p00 + p01;
                ls_hi += p10 + p11;
                uint32_t h0 = pack_bf2(p00, p01);
                uint32_t h1 = pack_bf2(p10, p11);
                __nv_bfloat162 hb0 = *(__nv_bfloat162*)&h0;
                __nv_bfloat162 hb1 = *(__nv_bfloat162*)&h1;
                uint32_t l0 = pack_bf2(p00 - __bfloat162float(hb0.x),
                                       p01 - __bfloat162float(hb0.y));
                uint32_t l1 = pack_bf2(p10 - __bfloat162float(hb1.x),
                                       p11 - __bfloat162float(hb1.y));
                ph[k2][half * 2 + 0] = h0; ph[k2][half * 2 + 1] = h1;
                pl[k2][half * 2 + 0] = l0; pl[k2][half * 2 + 1] = l1;
            }
        }
        ls_lo += __shfl_xor_sync(0xffffffffu, ls_lo, 1);
        ls_lo += __shfl_xor_sync(0xffffffffu, ls_lo, 2);
        ls_hi += __shfl_xor_sync(0xffffffffu, ls_hi, 1);
        ls_hi += __shfl_xor_sync(0xffffffffu, ls_hi, 2);
        l_lo = l_lo * corr_lo + ls_lo;
        l_hi = l_hi * corr_hi + ls_hi;
        m_lo = mt_lo; m_hi = mt_hi;

        #pragma unroll
        for (int nt = 0; nt < 16; ++nt) {
            oacc[nt][0] *= corr_lo; oacc[nt][1] *= corr_lo;
            oacc[nt][2] *= corr_hi; oacc[nt][3] *= corr_hi;
        }
        #pragma unroll
        for (int k2 = 0; k2 < 4; ++k2) {
            #pragma unroll
            for (int p2 = 0; p2 < 8; ++p2) {
                uint32_t vh4[4], vl4[4];
                uint32_t rb = sb + O_VH + (k2 * 16 + b_kr) * ATS + (p2 * 16 + b_no) * 2;
                ldmx4t(vh4, rb);
                ldmx4t(vl4, rb + (O_VL - O_VH));
                #pragma unroll
                for (int sub = 0; sub < 2; ++sub) {
                    int nt = p2 * 2 + sub;
                    uint32_t b0h = vh4[sub * 2], b1h = vh4[sub * 2 + 1];
                    uint32_t b0l = vl4[sub * 2], b1l = vl4[sub * 2 + 1];
                    MMA16816(oacc[nt], ph[k2], b0h, b1h);
                    MMA16816(oacc[nt], ph[k2], b0l, b1l);
                    MMA16816(oacc[nt], pl[k2], b0h, b1h);
                }
            }
        }
    }
    float rl0 = 1.f / l_lo, rl1 = 1.f / l_hi;
    #pragma unroll
    for (int nt = 0; nt < 16; ++nt) {
        int col = nt * 8 + (lane & 3) * 2;
        long o0 = ((long)(b * SEQ + r_lo)) * 2048 + h * 128 + col;
        long o1 = ((long)(b * SEQ + r_hi)) * 2048 + h * 128 + col;
        *(float2*)(O + o0) = make_float2(oacc[nt][0] * rl0, oacc[nt][1] * rl0);
        *(float2*)(O + o1) = make_float2(oacc[nt][2] * rl1, oacc[nt][3] * rl1);
    }
}

// --------------------------- TTT helper kernels -----------------------------
// W02 rows INTERLEAVED: row 2i = W0 row i, row 2i+1 = W2 row i.
__global__ void copyw(const float* __restrict__ w0, const float* __restrict__ w1,
                      const float* __restrict__ w2,
                      float* __restrict__ o02, float* __restrict__ o02t,
                      float* __restrict__ o1, float* __restrict__ o1t)
{
    long idx = (long)blockIdx.x * 256 + threadIdx.x;
    int col = idx & 511;
    int row = (idx >> 9) & 1023;
    int h = (idx >> 19) & 3;
    long src = (long)h * 262144 + (long)(row >> 1) * 512 + col;
    float v = (row & 1) ? w2[src] : w0[src];
    o02[idx] = v;
    o02t[idx] = to_tf32(v);
    if (idx < (long)2 * 1024 * 1024) {
        float v1 = w1[idx & ((long)4 * 262144 - 1)];
        o1[idx] = v1;
        o1t[idx] = to_tf32(v1);
    }
}

// gh interleaved: gate_i at 2i, hpre_i at 2i+1. dgp likewise.
__global__ void elem2(const float* __restrict__ fvt, const float* __restrict__ lr,
                      const float* __restrict__ gh, const float* __restrict__ dhin,
                      float* __restrict__ dgpt, float* __restrict__ vlt,
                      float* __restrict__ htt, int ck0)
{
    long idx = (long)blockIdx.x * 256 + threadIdx.x;
    int col = idx & 511;
    long tt = idx >> 9;
    int c = tt & 1023, bh = tt >> 10;
    int b = bh >> 2, h = bh & 3;
    long row = (long)b * SEQ + ck0 + c;
    float l0 = lr[row * 12 + h], l1 = lr[row * 12 + 4 + h], l2 = lr[row * 12 + 8 + h];
    long gi = (long)bh * 1048576 + (long)c * 1024 + 2 * col;
    float g = gh[gi], hp = gh[gi + 1], d = dhin[idx];
    float sig = 1.f / (1.f + expf(-g));
    float sg = g * sig;
    htt[idx] = to_tf32(sg * hp);
    float v = fvt[((long)bh * SEQ + ck0 + c) * FDM + col];
    dgpt[gi]     = to_tf32(d * hp * (sig * (1.f + g * (1.f - sig))) * l0);
    dgpt[gi + 1] = to_tf32(d * sg * l2);
    vlt[idx]     = to_tf32(v * l1);
}

// -------------------- ttt rmsnorm + add attention result --------------------
__global__ void post_kernel(const float* __restrict__ ttt, const float* __restrict__ tw,
                            const float* __restrict__ sum, float* __restrict__ smt)
{
    __shared__ float sr[4];
    int fh = blockIdx.x, row = blockIdx.y;
    int b = row >> 11, t = row & 2047;
    int bh = b * 4 + fh;
    const float* src = ttt + ((long)bh * SEQ + t) * FDM;
    int tid = threadIdx.x;
    float v[4], ss = 0.f;
    #pragma unroll
    for (int j = 0; j < 4; ++j) { v[j] = src[tid + 128 * j]; ss += v[j] * v[j]; }
    #pragma unroll
    for (int o = 16; o > 0; o >>= 1) ss += __shfl_down_sync(0xffffffffu, ss, o);
    if ((tid & 31) == 0) sr[tid >> 5] = ss;
    __syncthreads();
    float tot = sr[0] + sr[1] + sr[2] + sr[3];
    float r = rsqrtf(tot * (1.f / 512.f) + 1e-6f);
    #pragma unroll
    for (int j = 0; j < 4; ++j) {
        int i = tid + 128 * j;
        long o = (long)row * 2048 + fh * 512 + i;
        smt[o] = to_tf32(sum[o] + v[j] * r * tw[i]);
    }
}

// --------------------------------- launch -----------------------------------
#define GSYM(p, s) cudaGetSymbolAddress((void**)&(p), s)

extern "C" void kernel_launch(void* const* d_in, const int* in_sizes, int n_in,
                              void* d_out, int out_size)
{
    const float* hidden = (const float*)d_in[0];
    const float* Wqkv   = (const float*)d_in[1];
    const float* Wo     = (const float*)d_in[2];
    const float* qnw    = (const float*)d_in[3];
    const float* knw    = (const float*)d_in[4];
    const float* w0     = (const float*)d_in[5];
    const float* w1     = (const float*)d_in[6];
    const float* w2     = (const float*)d_in[7];
    const float* lrw    = (const float*)d_in[8];
    const float* lrb    = (const float*)d_in[9];
    const float* qksc   = (const float*)d_in[10];
    const float* qkof   = (const float*)d_in[11];
    const float* tttw   = (const float*)d_in[12];
    float* out = (float*)d_out;

    float *qkv, *lrpre, *lr, *pw02, *pw1, *gh, *dh, *ttt, *sum;
    GSYM(qkv, g_qkv);   GSYM(lrpre, g_lrpre); GSYM(lr, g_lr);
    GSYM(pw02, g_w02);  GSYM(pw1, g_w1);
    GSYM(gh, g_gh);     GSYM(dh, g_dh);
    GSYM(ttt, g_ttt);   GSYM(sum, g_sum);

    float *hxt,*wqt,*wot,*fqt,*fkt,*fvt,*w02t,*w1t,*dgpt,*vlt,*htt,*hnt,*smt;
    GSYM(hxt, g_hx_t); GSYM(wqt, g_wq_t); GSYM(wot, g_wo_t);
    GSYM(fqt, g_fq_t); GSYM(fkt, g_fk_t); GSYM(fvt, g_fv_t);
    GSYM(w02t, g_w02_t); GSYM(w1t, g_w1_t);
    GSYM(dgpt, g_dgp_t); GSYM(vlt, g_vl_t); GSYM(htt, g_ht_t);
    GSYM(hnt, g_hn_t); GSYM(smt, g_sm_t);

    __nv_bfloat16 *aqh,*aql,*akh,*akl,*avh,*avl;
    GSYM(aqh, g_aq_h); GSYM(aql, g_aq_l); GSYM(akh, g_ak_h); GSYM(akl, g_ak_l);
    GSYM(avh, g_av_h); GSYM(avl, g_av_l);

    cudaFuncSetAttribute(tf_nt, cudaFuncAttributeMaxDynamicSharedMemorySize, 110592);
    cudaFuncSetAttribute(tf_swi, cudaFuncAttributeMaxDynamicSharedMemorySize, 110592);
    cudaFuncSetAttribute(tf_pack_fwd, cudaFuncAttributeMaxDynamicSharedMemorySize, 110592);
    cudaFuncSetAttribute(tf_pack_upd, cudaFuncAttributeMaxDynamicSharedMemorySize, 104448);
    cudaFuncSetAttribute(tf_pack3, cudaFuncAttributeMaxDynamicSharedMemorySize, 110592);
    cudaFuncSetAttribute(attn_mma, cudaFuncAttributeMaxDynamicSharedMemorySize, ATTN_SMEM);

    cvt_tf<<<8192, 256>>>(hidden, hxt, (long)4096 * 2048);
    cvt_tf<<<12288, 256>>>(Wqkv, wqt, (long)6144 * 2048);
    cvt_tf<<<4096, 256>>>(Wo, wot, (long)2048 * 2048);

    {
        GP p{hxt, wqt, qkv, nullptr, 4096, 6144, 2048, 2048, 2048, 0, 0, 0, 48, 32};
        tf_nt<<<dim3(48, 32, 1), 256, 110592>>>(p);
    }
    lr_gemm<<<2048, 256>>>(hidden, lrw, lrpre);

    float base = (float)(0.001 + log(-expm1(-0.001)));
    prep_kernel<<<4096, 256>>>(qkv, lrpre, qnw, knw, qksc, qkof, lrb, base,
                               aqh, aql, akh, akl, avh, avl,
                               fqt, fkt, fvt, lr);
    attn_mma<<<dim3(32, 16, 2), 128, ATTN_SMEM>>>(aqh, aql, akh, akl, avh, avl, sum);

    copyw<<<16384, 256>>>(w0, w1, w2, pw02, w02t, pw1, w1t);

    long sSeq = (long)SEQ * FDM;
    long sChk = (long)1024 * FDM;
    long sW   = (long)FDM * FDM;
    long sW02 = (long)1024 * FDM;
    long sGH  = (long)1024 * 1024;

    // ---- chunk 0 ----
    {
        GP p1{fkt, w02t, gh, nullptr, 1024, 1024, 512, 512, 512, sSeq, sW02, sGH, 8, 8};
        GP p2{fvt, w1t, dh, nullptr, 1024, 512, 512, 512, 512, sSeq, sW, sChk, 4, 8};
        tf_pack_fwd<<<dim3(8, 8, 16), 256, 110592>>>(p1, p2, 8);
    }
    elem2<<<16384, 256>>>(fvt, lr, gh, dh, dgpt, vlt, htt, 0);
    {
        GP p1{dgpt, fkt, pw02, w02t, 1024, 512, 1024, 1024, 512, sGH, sSeq, sW02, 4, 8};
        GP p2{vlt, htt, pw1, w1t, 512, 512, 1024, 512, 512, sChk, sChk, sW, 4, 4};
        tf_pack_upd<<<dim3(4, 8, 16), 256, 104448>>>(p1, p2, 8);
    }
    {
        // qpass with fused SwiGLU epilogue: writes hnt [1024 x 512] directly
        GP p{fqt, w02t, hnt, hnt, 1024, 1024, 512, 512, 512, sSeq, sW02, sChk, 8, 8};
        tf_swi<<<dim3(8, 8, 8), 256, 110592>>>(p);
    }

    long co1 = (long)1024 * FDM;
    // ---- final(ck0) || fwd(ck1) packed ----
    {
        GP p1{hnt, w1t, ttt, nullptr, 1024, 512, 512, 512, 512, sChk, sW, sSeq, 4, 8};
        GP p2{fkt + co1, w02t, gh, nullptr, 1024, 1024, 512, 512, 512, sSeq, sW02, sGH, 8, 8};
        GP p3{fvt + co1, w1t, dh, nullptr, 1024, 512, 512, 512, 512, sSeq, sW, sChk, 4, 8};
        tf_pack3<<<dim3(8, 8, 24), 256, 110592>>>(p1, p2, p3, 8, 8);
    }
    // ---- chunk 1 ----
    elem2<<<16384, 256>>>(fvt, lr, gh, dh, dgpt, vlt, htt, 1024);
    {
        GP p1{dgpt, fkt + co1, pw02, w02t, 1024, 512, 1024, 1024, 512, sGH, sSeq, sW02, 4, 8};
        GP p2{vlt, htt, pw1, w1t, 512, 512, 1024, 512, 512, sChk, sChk, sW, 4, 4};
        tf_pack_upd<<<dim3(4, 8, 16), 256, 104448>>>(p1, p2, 8);
    }
    {
        GP p{fqt + co1, w02t, hnt, hnt, 1024, 1024, 512, 512, 512, sSeq, sW02, sChk, 8, 8};
        tf_swi<<<dim3(8, 8, 8), 256, 110592>>>(p);
    }
    {
        GP p{hnt, w1t, ttt + co1, nullptr, 1024, 512, 512, 512, 512, sChk, sW, sSeq, 4, 8};
        tf_nt<<<dim3(4, 8, 8), 256, 110592>>>(p);
    }

    post_kernel<<<dim3(4, 4096), 128>>>(ttt, tttw, sum, smt);
    {
        GP p{smt, wot, out, nullptr, 4096, 2048, 2048, 2048, 2048, 0, 0, 0, 16, 32};
        tf_nt<<<dim3(16, 32, 1), 256, 110592>>>(p);
    }
}